// round 4
// baseline (speedup 1.0000x reference)
#include <cuda_runtime.h>

// Problem constants (fixed by setup_inputs)
#define BB    8192      // batch
#define DD    2048      // feature dim
#define NNODE 255       // inner nodes (2^8 - 1)
#define PSTR  256       // padded stride for p
#define NLEAF 256
#define NC    128       // classes

// ---------------- scratch (device globals; no dynamic allocation) ----------
__device__ float g_p[BB * PSTR];        // sigmoid gate per (sample, node)
__device__ float g_Q[NLEAF * NC];       // softmax(leaf_params)
__device__ float g_logQt[NC * NLEAF];   // transposed logQ: [class][leaf]
__device__ float g_pen_num[128];        // per-node  sum_b p*path   (nodes 0..126 used)
__device__ float g_pen_den[128];        // per-node  sum_b path
__device__ float g_loss;                // sum_b sum_leaf path*logQ[leaf, target]

// ---------------- init ------------------------------------------------------
__global__ void k_init() {
    int t = threadIdx.x;
    if (t < 128) { g_pen_num[t] = 0.f; g_pen_den[t] = 0.f; }
    if (t == 0) g_loss = 0.f;
}

// ---------------- GEMM + bias + beta + sigmoid ------------------------------
// C[b][j] = sigmoid(beta[j] * (x[b,:] . W[j,:] + bias[j])), j < 255
// BM=128, BN=64, BK=8, 256 threads, 8x4 microtile, smem ping-pong.
#define BM 128
#define BN 64
#define BK 8

__global__ __launch_bounds__(256)
void k_gemm(const float* __restrict__ x, const float* __restrict__ W,
            const float* __restrict__ bias, const float* __restrict__ beta)
{
    __shared__ __align__(16) float As[2][BK][BM + 4];   // [k][m], row=132 floats (16B-aligned)
    __shared__ __align__(16) float Bs[2][BK][BN + 4];   // [k][n], row=68 floats  (16B-aligned)

    const int tid     = threadIdx.x;
    const int rowBase = blockIdx.y * BM;
    const int colBase = blockIdx.x * BN;

    // A-tile load map: 256 threads, each 1x float4. 128 rows x 8 k, 2 float4/row.
    const int aRow = tid >> 1;            // 0..127
    const int aK   = (tid & 1) * 4;       // 0 or 4
    // B-tile load map: 256 threads, each 1x float2. 64 rows x 8 k, 4 float2/row.
    const int bRow = tid >> 2;            // 0..63
    const int bK   = (tid & 3) * 2;       // 0,2,4,6

    // compute map: 16x16 thread grid -> 8 rows x 4 cols per thread
    const int mBase = (tid >> 4) * 8;
    const int nBase = (tid & 15) * 4;

    const float* xg = x + (rowBase + aRow) * DD + aK;
    const bool  bValid = (colBase + bRow) < NNODE;
    const float* wg = W + (bValid ? (colBase + bRow) : 0) * DD + bK;

    float acc[8][4];
    #pragma unroll
    for (int i = 0; i < 8; ++i)
        #pragma unroll
        for (int j = 0; j < 4; ++j) acc[i][j] = 0.f;

    // prologue: tile 0
    {
        float4 a = *reinterpret_cast<const float4*>(xg);
        float2 b = bValid ? *reinterpret_cast<const float2*>(wg) : make_float2(0.f, 0.f);
        As[0][aK + 0][aRow] = a.x; As[0][aK + 1][aRow] = a.y;
        As[0][aK + 2][aRow] = a.z; As[0][aK + 3][aRow] = a.w;
        Bs[0][bK + 0][bRow] = b.x; Bs[0][bK + 1][bRow] = b.y;
    }
    __syncthreads();

    const int NT = DD / BK;   // 256
    int cur = 0;
    for (int kt = 0; kt < NT; ++kt) {
        float4 a_nxt; float2 b_nxt;
        const bool more = (kt + 1 < NT);
        if (more) {
            a_nxt = *reinterpret_cast<const float4*>(xg + (kt + 1) * BK);
            b_nxt = bValid ? *reinterpret_cast<const float2*>(wg + (kt + 1) * BK)
                           : make_float2(0.f, 0.f);
        }
        #pragma unroll
        for (int kk = 0; kk < BK; ++kk) {
            float4 a0 = *reinterpret_cast<const float4*>(&As[cur][kk][mBase]);
            float4 a1 = *reinterpret_cast<const float4*>(&As[cur][kk][mBase + 4]);
            float4 bv = *reinterpret_cast<const float4*>(&Bs[cur][kk][nBase]);
            float av[8] = {a0.x, a0.y, a0.z, a0.w, a1.x, a1.y, a1.z, a1.w};
            float bw[4] = {bv.x, bv.y, bv.z, bv.w};
            #pragma unroll
            for (int i = 0; i < 8; ++i)
                #pragma unroll
                for (int j = 0; j < 4; ++j)
                    acc[i][j] = fmaf(av[i], bw[j], acc[i][j]);
        }
        if (more) {
            int nxt = cur ^ 1;
            As[nxt][aK + 0][aRow] = a_nxt.x; As[nxt][aK + 1][aRow] = a_nxt.y;
            As[nxt][aK + 2][aRow] = a_nxt.z; As[nxt][aK + 3][aRow] = a_nxt.w;
            Bs[nxt][bK + 0][bRow] = b_nxt.x; Bs[nxt][bK + 1][bRow] = b_nxt.y;
            cur = nxt;
        }
        __syncthreads();
    }

    // epilogue: bias, beta, sigmoid, store to padded p
    #pragma unroll
    for (int j = 0; j < 4; ++j) {
        int c = colBase + nBase + j;
        if (c < NNODE) {
            float bb = bias[c];
            float bt = beta[c];
            #pragma unroll
            for (int i = 0; i < 8; ++i) {
                int m = rowBase + mBase + i;
                float z = bt * (acc[i][j] + bb);
                g_p[m * PSTR + c] = 1.f / (1.f + expf(-z));
            }
        }
    }
}

// ---------------- leaf softmax (Q and transposed logQ) -----------------------
__global__ void k_softmax(const float* __restrict__ lp)
{
    __shared__ float redm[4], reds[4];
    int leaf = blockIdx.x, c = threadIdx.x;    // 128 threads
    int lane = c & 31, w = c >> 5;
    float v = lp[leaf * NC + c];
    float m = v;
    #pragma unroll
    for (int off = 16; off; off >>= 1) m = fmaxf(m, __shfl_xor_sync(0xffffffffu, m, off));
    if (lane == 0) redm[w] = m;
    __syncthreads();
    m = fmaxf(fmaxf(redm[0], redm[1]), fmaxf(redm[2], redm[3]));
    float e = expf(v - m);
    float s = e;
    #pragma unroll
    for (int off = 16; off; off >>= 1) s += __shfl_xor_sync(0xffffffffu, s, off);
    if (lane == 0) reds[w] = s;
    __syncthreads();
    s = reds[0] + reds[1] + reds[2] + reds[3];
    g_Q[leaf * NC + c] = e / s;
    g_logQt[c * NLEAF + leaf] = v - m - logf(s);
}

// ---------------- path propagation / penalties / loss / argmax / output -----
#define SPB 16   // samples per block

__global__ __launch_bounds__(256)
void k_path(const int* __restrict__ target, float* __restrict__ out, int outOffset)
{
    __shared__ float bufA[SPB][257];   // padded stride -> conflict-free
    __shared__ float bufB[SPB][257];
    __shared__ float s_num[128];
    __shared__ float s_den[128];
    __shared__ float s_loss;
    __shared__ int   s_leaf[SPB];

    const int tid = threadIdx.x;
    const int s0  = blockIdx.x * SPB;

    if (tid < 127) { s_num[tid] = 0.f; s_den[tid] = 0.f; }
    if (tid == 0)  s_loss = 0.f;
    if (tid < SPB) bufA[tid][0] = 1.0f;
    __syncthreads();

    // levels: path for depth d sits in bufA (d even) / bufB (d odd)
    for (int d = 0; d < 8; ++d) {
        const int n = 1 << d;
        const int start = n - 1;
        float (*cur)[257] = (d & 1) ? bufB : bufA;
        float (*nxt)[257] = (d & 1) ? bufA : bufB;
        const int total = SPB * n;
        for (int idx = tid; idx < total; idx += 256) {
            int s = idx >> d;
            int i = idx & (n - 1);
            float path = cur[s][i];
            float pv   = g_p[(s0 + s) * PSTR + start + i];
            if (d < 7) {  // penalties only used for depths 0..6
                atomicAdd(&s_num[start + i], pv * path);
                atomicAdd(&s_den[start + i], path);
            }
            nxt[s][2 * i]     = path * (1.f - pv);
            nxt[s][2 * i + 1] = path * pv;
        }
        __syncthreads();
    }
    // final 256-wide path is in bufA (last write had d=7 odd -> nxt = bufA)

    // loss + argmax: 16 threads per sample, 16 leaves each (strided)
    {
        int s = tid >> 4;
        int l = tid & 15;
        int t = target[s0 + s];
        const float* lq = g_logQt + t * NLEAF;
        float lsum = 0.f;
        float bv = -1.f; int bi = 0;
        #pragma unroll
        for (int k = 0; k < 16; ++k) {
            int i = l + (k << 4);
            float pw = bufA[s][i];
            lsum += pw * lq[i];
            if (pw > bv) { bv = pw; bi = i; }   // strict '>' keeps first index
        }
        #pragma unroll
        for (int off = 8; off > 0; off >>= 1) {
            float ov = __shfl_down_sync(0xffffffffu, bv,   off, 16);
            int   oi = __shfl_down_sync(0xffffffffu, bi,   off, 16);
            float os = __shfl_down_sync(0xffffffffu, lsum, off, 16);
            lsum += os;
            if (ov > bv || (ov == bv && oi < bi)) { bv = ov; bi = oi; }
        }
        if (l == 0) {
            s_leaf[s] = bi;
            atomicAdd(&s_loss, lsum);
        }
    }
    __syncthreads();

    // output rows: out[s] = Q[leaf_idx[s]]
    for (int idx = tid; idx < SPB * NC; idx += 256) {
        int s = idx >> 7;
        int c = idx & 127;
        out[outOffset + (s0 + s) * NC + c] = g_Q[s_leaf[s] * NC + c];
    }

    if (tid < 127) {
        atomicAdd(&g_pen_num[tid], s_num[tid]);
        atomicAdd(&g_pen_den[tid], s_den[tid]);
    }
    if (tid == 0) atomicAdd(&g_loss, s_loss);
}

// ---------------- finalize: total = -loss + Cpen -----------------------------
__global__ void k_final(float* __restrict__ out, int writeTotal)
{
    if (threadIdx.x != 0 || blockIdx.x != 0) return;
    float loss = g_loss / (float)BB;
    float Cpen = 0.f;
    int node = 0;
    for (int d = 0; d < 7; ++d) {
        float lam = 0.1f * exp2f(-(float)(d + 1));
        int n = 1 << d;
        float acc = 0.f;
        for (int i = 0; i < n; ++i, ++node) {
            float pen = g_pen_num[node] / g_pen_den[node];
            acc += logf(pen) + logf(1.f - pen);
        }
        Cpen -= lam * 0.5f * acc;
    }
    float total = -loss + Cpen;
    if (writeTotal) out[0] = total;
}

// ---------------- launch -----------------------------------------------------
extern "C" void kernel_launch(void* const* d_in, const int* in_sizes, int n_in,
                              void* d_out, int out_size)
{
    const float* x      = (const float*)d_in[0];
    const int*   target = (const int*)  d_in[1];
    const float* W      = (const float*)d_in[2];
    const float* bias   = (const float*)d_in[3];
    const float* beta   = (const float*)d_in[4];
    const float* leafp  = (const float*)d_in[5];
    float* out = (float*)d_out;

    // tuple output (total, output): total scalar first, then B*C matrix
    int offset = out_size - BB * NC;
    if (offset < 0) offset = 0;

    k_init<<<1, 128>>>();

    dim3 gg((NNODE + BN - 1) / BN, BB / BM);   // (4, 64)
    k_gemm<<<gg, 256>>>(x, W, bias, beta);

    k_softmax<<<NLEAF, NC>>>(leafp);

    k_path<<<BB / SPB, 256>>>(target, out, offset);

    k_final<<<1, 32>>>(out, offset >= 1 ? 1 : 0);
}

// round 10
// speedup vs baseline: 1.3359x; 1.3359x over previous
#include <cuda_runtime.h>
#include <cstdint>

// Problem constants (fixed by setup_inputs)
#define BB    8192      // batch
#define DD    2048      // feature dim
#define NNODE 255       // inner nodes (2^8 - 1)
#define PSTR  256       // padded stride for p
#define NLEAF 256
#define NC    128       // classes

// ---------------- scratch (device globals; no dynamic allocation) ----------
__device__ float g_p[BB * PSTR];        // sigmoid gate per (sample, node)
__device__ float g_Q[NLEAF * NC];       // softmax(leaf_params)
__device__ float g_logQt[NC * NLEAF];   // transposed logQ: [class][leaf]
__device__ float g_pen_num[128];
__device__ float g_pen_den[128];
__device__ float g_loss;

// ---------------- init ------------------------------------------------------
__global__ void k_init() {
    int t = threadIdx.x;
    if (t < 128) { g_pen_num[t] = 0.f; g_pen_den[t] = 0.f; }
    if (t == 0) g_loss = 0.f;
}

// ================== legacy tensor-core GEMM (mma.sync tf32) =================
// logits[b][j] = x[b,:] . W[j,:]; epilogue: g_p = sigmoid(beta*(logit+bias))
// 3xTF32: acc += Ahi*Bhi + Ahi*Blo + Alo*Bhi  (fp32 accumulate)
// CTA: 512 thr, 16 warps (4x4), block tile 128x128, warp tile 32x32, KC=32.

#define KC    32
#define NCHK  (DD / KC)     // 64
#define TSTR  36            // padded smem row stride (floats): conflict-free frags
#define TILEF (128 * TSTR)  // 4608 floats per tile buffer

// fp32 -> (tf32 hi, tf32 lo)
__device__ __forceinline__ void split_tf32(float v, uint32_t& hi, uint32_t& lo) {
    uint32_t h; asm("cvt.rna.tf32.f32 %0, %1;" : "=r"(h) : "f"(v));
    float r = v - __uint_as_float(h);
    uint32_t l; asm("cvt.rna.tf32.f32 %0, %1;" : "=r"(l) : "f"(r));
    hi = h; lo = l;
}

__device__ __forceinline__ void mma_tf32(float* c, const uint32_t* a, const uint32_t* b) {
    asm volatile(
        "mma.sync.aligned.m16n8k8.row.col.f32.tf32.tf32.f32 "
        "{%0,%1,%2,%3}, {%4,%5,%6,%7}, {%8,%9}, {%0,%1,%2,%3};"
        : "+f"(c[0]), "+f"(c[1]), "+f"(c[2]), "+f"(c[3])
        : "r"(a[0]), "r"(a[1]), "r"(a[2]), "r"(a[3]), "r"(b[0]), "r"(b[1]));
}

__global__ __launch_bounds__(512, 1)
void k_gemm(const float* __restrict__ x, const float* __restrict__ W,
            const float* __restrict__ bias, const float* __restrict__ beta)
{
    extern __shared__ float dynsmem[];          // [2*TILEF A][2*TILEF B]
    __shared__ float bias_sh[128], beta_sh[128];

    const int tid  = threadIdx.x;
    const int lane = tid & 31;
    const int wid  = tid >> 5;
    const int wm   = wid & 3;                   // warp M group (0..3)
    const int wn   = wid >> 2;                  // warp N group (0..3)
    const int rowBase = blockIdx.y * 128;
    const int colBase = blockIdx.x * 128;

    float* Abuf = dynsmem;                      // [2][128][TSTR]
    float* Bbuf = dynsmem + 2 * TILEF;          // [2][128][TSTR]

    if (tid < 128) {
        int c = colBase + tid;
        bias_sh[tid] = (c < NNODE) ? bias[c] : 0.f;
        beta_sh[tid] = (c < NNODE) ? beta[c] : 0.f;
    }

    // -------- global load map: thread -> (row, two float4s of a 32-wide chunk)
    const int ldRow = tid >> 2;                 // 0..127
    const int ldK   = (tid & 3) * 4;            // float col 0,4,8,12 (second +16)
    const float* pA = x + (size_t)(rowBase + ldRow) * DD + ldK;
    int nrow = colBase + ldRow;
    if (nrow >= NNODE) nrow = 0;                // clamp; results masked in epilogue
    const float* pB = W + (size_t)nrow * DD + ldK;
    const int sOff  = ldRow * TSTR + ldK;       // smem float offset (16B-aligned)

    float acc[2][4][4];
    #pragma unroll
    for (int mt = 0; mt < 2; ++mt)
        #pragma unroll
        for (int nt = 0; nt < 4; ++nt)
            #pragma unroll
            for (int q = 0; q < 4; ++q) acc[mt][nt][q] = 0.f;

    // -------- prologue: chunk 0 -> buffer 0
    {
        float4 a0 = *reinterpret_cast<const float4*>(pA);
        float4 a1 = *reinterpret_cast<const float4*>(pA + 16);
        float4 b0 = *reinterpret_cast<const float4*>(pB);
        float4 b1 = *reinterpret_cast<const float4*>(pB + 16);
        *reinterpret_cast<float4*>(Abuf + sOff)      = a0;
        *reinterpret_cast<float4*>(Abuf + sOff + 16) = a1;
        *reinterpret_cast<float4*>(Bbuf + sOff)      = b0;
        *reinterpret_cast<float4*>(Bbuf + sOff + 16) = b1;
    }
    __syncthreads();

    const int ar = wm * 32 + (lane >> 2);       // A fragment base row (block-local)
    const int bn = wn * 32 + (lane >> 2);       // B fragment base col (block-local)
    const int kl = lane & 3;                    // k offset within slice

    int cur = 0;
    for (int kt = 0; kt < NCHK; ++kt) {
        const bool more = (kt + 1 < NCHK);
        float4 a0, a1, b0, b1;
        if (more) {
            a0 = *reinterpret_cast<const float4*>(pA + (kt + 1) * KC);
            a1 = *reinterpret_cast<const float4*>(pA + (kt + 1) * KC + 16);
            b0 = *reinterpret_cast<const float4*>(pB + (kt + 1) * KC);
            b1 = *reinterpret_cast<const float4*>(pB + (kt + 1) * KC + 16);
        }

        const float* Ab = Abuf + cur * TILEF;
        const float* Bb = Bbuf + cur * TILEF;

        #pragma unroll
        for (int ks = 0; ks < 4; ++ks) {
            const int kc = ks * 8 + kl;
            // A fragments (hi/lo)
            uint32_t ahi[2][4], alo[2][4];
            #pragma unroll
            for (int mt = 0; mt < 2; ++mt) {
                const float* ap = Ab + (ar + mt * 16) * TSTR + kc;
                float v0 = ap[0];
                float v1 = ap[8 * TSTR];
                float v2 = ap[4];
                float v3 = ap[8 * TSTR + 4];
                split_tf32(v0, ahi[mt][0], alo[mt][0]);
                split_tf32(v1, ahi[mt][1], alo[mt][1]);
                split_tf32(v2, ahi[mt][2], alo[mt][2]);
                split_tf32(v3, ahi[mt][3], alo[mt][3]);
            }
            // B fragments (hi/lo)
            uint32_t bhi[4][2], blo[4][2];
            #pragma unroll
            for (int nt = 0; nt < 4; ++nt) {
                const float* bp = Bb + (bn + nt * 8) * TSTR + kc;
                float u0 = bp[0];
                float u1 = bp[4];
                split_tf32(u0, bhi[nt][0], blo[nt][0]);
                split_tf32(u1, bhi[nt][1], blo[nt][1]);
            }
            // 3xTF32 MMAs
            #pragma unroll
            for (int mt = 0; mt < 2; ++mt)
                #pragma unroll
                for (int nt = 0; nt < 4; ++nt) {
                    mma_tf32(acc[mt][nt], ahi[mt], bhi[nt]);
                    mma_tf32(acc[mt][nt], ahi[mt], blo[nt]);
                    mma_tf32(acc[mt][nt], alo[mt], bhi[nt]);
                }
        }

        if (more) {
            float* An = Abuf + (cur ^ 1) * TILEF;
            float* Bn = Bbuf + (cur ^ 1) * TILEF;
            *reinterpret_cast<float4*>(An + sOff)      = a0;
            *reinterpret_cast<float4*>(An + sOff + 16) = a1;
            *reinterpret_cast<float4*>(Bn + sOff)      = b0;
            *reinterpret_cast<float4*>(Bn + sOff + 16) = b1;
        }
        __syncthreads();
        cur ^= 1;
    }

    // -------- epilogue: bias/beta/sigmoid -> g_p
    #pragma unroll
    for (int mt = 0; mt < 2; ++mt) {
        const int row = rowBase + wm * 32 + mt * 16 + (lane >> 2);
        #pragma unroll
        for (int nt = 0; nt < 4; ++nt) {
            const int cl  = wn * 32 + nt * 8 + 2 * (lane & 3);   // block-local col
            const int col = colBase + cl;
            const float bb0 = bias_sh[cl],     bt0 = beta_sh[cl];
            const float bb1 = bias_sh[cl + 1], bt1 = beta_sh[cl + 1];
            float z0 = bt0 * (acc[mt][nt][0] + bb0);
            float z1 = bt1 * (acc[mt][nt][1] + bb1);
            float z2 = bt0 * (acc[mt][nt][2] + bb0);
            float z3 = bt1 * (acc[mt][nt][3] + bb1);
            float s0 = 1.f / (1.f + expf(-z0));
            float s1 = 1.f / (1.f + expf(-z1));
            float s2 = 1.f / (1.f + expf(-z2));
            float s3 = 1.f / (1.f + expf(-z3));
            if (col + 1 < NNODE) {
                *reinterpret_cast<float2*>(&g_p[(size_t)row * PSTR + col])       = make_float2(s0, s1);
                *reinterpret_cast<float2*>(&g_p[(size_t)(row + 8) * PSTR + col]) = make_float2(s2, s3);
            } else if (col < NNODE) {
                g_p[(size_t)row * PSTR + col]       = s0;
                g_p[(size_t)(row + 8) * PSTR + col] = s2;
            }
        }
    }
}

// ---------------- leaf softmax (Q and transposed logQ) -----------------------
__global__ void k_softmax(const float* __restrict__ lp)
{
    __shared__ float redm[4], reds[4];
    int leaf = blockIdx.x, c = threadIdx.x;    // 128 threads
    int lane = c & 31, w = c >> 5;
    float v = lp[leaf * NC + c];
    float m = v;
    #pragma unroll
    for (int off = 16; off; off >>= 1) m = fmaxf(m, __shfl_xor_sync(0xffffffffu, m, off));
    if (lane == 0) redm[w] = m;
    __syncthreads();
    m = fmaxf(fmaxf(redm[0], redm[1]), fmaxf(redm[2], redm[3]));
    float e = expf(v - m);
    float s = e;
    #pragma unroll
    for (int off = 16; off; off >>= 1) s += __shfl_xor_sync(0xffffffffu, s, off);
    if (lane == 0) reds[w] = s;
    __syncthreads();
    s = reds[0] + reds[1] + reds[2] + reds[3];
    g_Q[leaf * NC + c] = e / s;
    g_logQt[c * NLEAF + leaf] = v - m - logf(s);
}

// ---------------- path propagation / penalties / loss / argmax / output -----
#define SPB 16   // samples per block

__global__ __launch_bounds__(256)
void k_path(const int* __restrict__ target, float* __restrict__ out, int outOffset)
{
    __shared__ float bufA[SPB][257];
    __shared__ float bufB[SPB][257];
    __shared__ float s_num[128];
    __shared__ float s_den[128];
    __shared__ float s_loss;
    __shared__ int   s_leaf[SPB];

    const int tid = threadIdx.x;
    const int s0  = blockIdx.x * SPB;

    if (tid < 127) { s_num[tid] = 0.f; s_den[tid] = 0.f; }
    if (tid == 0)  s_loss = 0.f;
    if (tid < SPB) bufA[tid][0] = 1.0f;
    __syncthreads();

    for (int d = 0; d < 8; ++d) {
        const int n = 1 << d;
        const int start = n - 1;
        float (*cur)[257] = (d & 1) ? bufB : bufA;
        float (*nxt)[257] = (d & 1) ? bufA : bufB;
        const int total = SPB * n;
        for (int idx = tid; idx < total; idx += 256) {
            int s = idx >> d;
            int i = idx & (n - 1);
            float path = cur[s][i];
            float pv   = g_p[(s0 + s) * PSTR + start + i];
            if (d < 7) {
                atomicAdd(&s_num[start + i], pv * path);
                atomicAdd(&s_den[start + i], path);
            }
            nxt[s][2 * i]     = path * (1.f - pv);
            nxt[s][2 * i + 1] = path * pv;
        }
        __syncthreads();
    }

    {
        int s = tid >> 4;
        int l = tid & 15;
        int t = target[s0 + s];
        const float* lq = g_logQt + t * NLEAF;
        float lsum = 0.f;
        float bv = -1.f; int bi = 0;
        #pragma unroll
        for (int k = 0; k < 16; ++k) {
            int i = l + (k << 4);
            float pw = bufA[s][i];
            lsum += pw * lq[i];
            if (pw > bv) { bv = pw; bi = i; }
        }
        #pragma unroll
        for (int off = 8; off > 0; off >>= 1) {
            float ov = __shfl_down_sync(0xffffffffu, bv,   off, 16);
            int   oi = __shfl_down_sync(0xffffffffu, bi,   off, 16);
            float os = __shfl_down_sync(0xffffffffu, lsum, off, 16);
            lsum += os;
            if (ov > bv || (ov == bv && oi < bi)) { bv = ov; bi = oi; }
        }
        if (l == 0) {
            s_leaf[s] = bi;
            atomicAdd(&s_loss, lsum);
        }
    }
    __syncthreads();

    for (int idx = tid; idx < SPB * NC; idx += 256) {
        int s = idx >> 7;
        int c = idx & 127;
        out[outOffset + (s0 + s) * NC + c] = g_Q[s_leaf[s] * NC + c];
    }

    if (tid < 127) {
        atomicAdd(&g_pen_num[tid], s_num[tid]);
        atomicAdd(&g_pen_den[tid], s_den[tid]);
    }
    if (tid == 0) atomicAdd(&g_loss, s_loss);
}

// ---------------- finalize: total = -loss + Cpen -----------------------------
__global__ void k_final(float* __restrict__ out, int writeTotal)
{
    if (threadIdx.x != 0 || blockIdx.x != 0) return;
    float loss = g_loss / (float)BB;
    float Cpen = 0.f;
    int node = 0;
    for (int d = 0; d < 7; ++d) {
        float lam = 0.1f * exp2f(-(float)(d + 1));
        int n = 1 << d;
        float acc = 0.f;
        for (int i = 0; i < n; ++i, ++node) {
            float pen = g_pen_num[node] / g_pen_den[node];
            acc += logf(pen) + logf(1.f - pen);
        }
        Cpen -= lam * 0.5f * acc;
    }
    float total = -loss + Cpen;
    if (writeTotal) out[0] = total;
}

// ---------------- launch -----------------------------------------------------
extern "C" void kernel_launch(void* const* d_in, const int* in_sizes, int n_in,
                              void* d_out, int out_size)
{
    const float* x      = (const float*)d_in[0];
    const int*   target = (const int*)  d_in[1];
    const float* W      = (const float*)d_in[2];
    const float* bias   = (const float*)d_in[3];
    const float* beta   = (const float*)d_in[4];
    const float* leafp  = (const float*)d_in[5];
    float* out = (float*)d_out;

    int offset = out_size - BB * NC;
    if (offset < 0) offset = 0;

    const int dynBytes = 4 * TILEF * (int)sizeof(float);   // 73728 B
    cudaFuncSetAttribute(k_gemm, cudaFuncAttributeMaxDynamicSharedMemorySize, dynBytes);

    k_init<<<1, 128>>>();

    dim3 gg(2, BB / 128);   // (2 N-tiles, 64 M-tiles) = 128 CTAs
    k_gemm<<<gg, 512, dynBytes>>>(x, W, bias, beta);

    k_softmax<<<NLEAF, NC>>>(leafp);

    k_path<<<BB / SPB, 256>>>(target, out, offset);

    k_final<<<1, 32>>>(out, offset >= 1 ? 1 : 0);
}

// round 11
// speedup vs baseline: 1.8021x; 1.3490x over previous
#include <cuda_runtime.h>
#include <cuda_fp16.h>
#include <cstdint>

// Problem constants (fixed by setup_inputs)
#define BB    8192      // batch
#define DD    2048      // feature dim
#define NNODE 255       // inner nodes (2^8 - 1)
#define PSTR  256       // padded stride for p
#define NLEAF 256
#define NC    128       // classes

// ---------------- scratch (device globals; no dynamic allocation) ----------
__device__ float g_p[BB * PSTR];        // sigmoid gate per (sample, node)
__device__ float g_Q[NLEAF * NC];       // softmax(leaf_params)
__device__ float g_logQt[NC * NLEAF];   // transposed logQ: [class][leaf]
__device__ float g_pen_num[128];
__device__ float g_pen_den[128];
__device__ float g_loss;

// ---------------- init ------------------------------------------------------
__global__ void k_init() {
    int t = threadIdx.x;
    if (t < 128) { g_pen_num[t] = 0.f; g_pen_den[t] = 0.f; }
    if (t == 0) g_loss = 0.f;
}

// ================= fp16x3 tensor-core GEMM (mma.sync m16n8k16) ==============
// logits[b][j] = x[b,:].W[j,:]; epilogue: g_p = sigmoid(beta*(logit+bias))
// Split v = h + l (h = fp16 RN), store l' = l*2048 (always fp16-normal).
// acc  = Ah*Bh            (main, fp32 accum)
// corr = Ah*Bl' + Al'*Bh  (corrections, scaled by 2048)
// final = acc + corr * 2^-11.  Dropped l*l term ~2^-22 -> logit err ~1.6e-7.
// CTA: 512 thr, 16 warps (4x4), block tile 128x128, warp tile 32x32, KC=16.

#define KC     16
#define NCHK   (DD / KC)        // 128
#define SH     24               // smem row stride in halves (12 words: conflict-free)
#define TILEH  (128 * SH)       // 3072 halves per tile
#define STAGEH (4 * TILEH)      // Ah, Al, Bh, Bl
#define DYNSME (2 * STAGEH * 2) // bytes: 2 stages * halves * 2B = 49152

__device__ __forceinline__ void mma_f16(float* c, const uint32_t* a, const uint32_t* b) {
    asm volatile(
        "mma.sync.aligned.m16n8k16.row.col.f32.f16.f16.f32 "
        "{%0,%1,%2,%3}, {%4,%5,%6,%7}, {%8,%9}, {%0,%1,%2,%3};"
        : "+f"(c[0]), "+f"(c[1]), "+f"(c[2]), "+f"(c[3])
        : "r"(a[0]), "r"(a[1]), "r"(a[2]), "r"(a[3]), "r"(b[0]), "r"(b[1]));
}

// split float4 -> hi half2x2 and (lo*2048) half2x2, store as uint2 each
__device__ __forceinline__ void cvt_store(float4 f, __half* hdst, __half* ldst) {
    __half2 h0 = __floats2half2_rn(f.x, f.y);
    __half2 h1 = __floats2half2_rn(f.z, f.w);
    float2 g0 = __half22float2(h0);
    float2 g1 = __half22float2(h1);
    __half2 l0 = __floats2half2_rn((f.x - g0.x) * 2048.f, (f.y - g0.y) * 2048.f);
    __half2 l1 = __floats2half2_rn((f.z - g1.x) * 2048.f, (f.w - g1.y) * 2048.f);
    uint2 hu, lu;
    hu.x = *reinterpret_cast<uint32_t*>(&h0);
    hu.y = *reinterpret_cast<uint32_t*>(&h1);
    lu.x = *reinterpret_cast<uint32_t*>(&l0);
    lu.y = *reinterpret_cast<uint32_t*>(&l1);
    *reinterpret_cast<uint2*>(hdst) = hu;
    *reinterpret_cast<uint2*>(ldst) = lu;
}

__global__ __launch_bounds__(512, 1)
void k_gemm(const float* __restrict__ x, const float* __restrict__ W,
            const float* __restrict__ bias, const float* __restrict__ beta)
{
    extern __shared__ __half dynsmem[];
    __shared__ float bias_sh[128], beta_sh[128];

    const int tid  = threadIdx.x;
    const int lane = tid & 31;
    const int wid  = tid >> 5;
    const int wm   = wid & 3;                   // warp M group (0..3)
    const int wn   = wid >> 2;                  // warp N group (0..3)
    const int rowBase = blockIdx.y * 128;
    const int colBase = blockIdx.x * 128;

    if (tid < 128) {
        int c = colBase + tid;
        bias_sh[tid] = (c < NNODE) ? bias[c] : 0.f;
        beta_sh[tid] = (c < NNODE) ? beta[c] : 0.f;
    }

    // -------- global load map: 512 thr, each one float4 of A and of B per chunk
    const int ldRow = tid >> 2;                 // 0..127
    const int ldK   = (tid & 3) * 4;            // 0,4,8,12
    const float* pA = x + (size_t)(rowBase + ldRow) * DD + ldK;
    int nrow = colBase + ldRow;
    if (nrow >= NNODE) nrow = 0;                // clamp; masked in epilogue
    const float* pB = W + (size_t)nrow * DD + ldK;
    const int sOff  = ldRow * SH + ldK;         // half offset within a tile

    float acc[2][4][4], corr[2][4][4];
    #pragma unroll
    for (int mt = 0; mt < 2; ++mt)
        #pragma unroll
        for (int nt = 0; nt < 4; ++nt)
            #pragma unroll
            for (int q = 0; q < 4; ++q) { acc[mt][nt][q] = 0.f; corr[mt][nt][q] = 0.f; }

    // -------- prologue: chunk 0 -> stage 0
    {
        float4 fa = *reinterpret_cast<const float4*>(pA);
        float4 fb = *reinterpret_cast<const float4*>(pB);
        __half* Ah = dynsmem;
        cvt_store(fa, Ah + sOff,             Ah + TILEH + sOff);
        cvt_store(fb, Ah + 2 * TILEH + sOff, Ah + 3 * TILEH + sOff);
    }
    __syncthreads();

    const int g = lane >> 2;                    // fragment group row/col
    const int t = lane & 3;
    const int arw = wm * 32 + g;                // A row base (block-local)
    const int bcl = wn * 32 + g;                // B col base (block-local)

    int cur = 0;
    for (int kt = 0; kt < NCHK; ++kt) {
        const bool more = (kt + 1 < NCHK);
        float4 fa, fb;
        if (more) {
            fa = *reinterpret_cast<const float4*>(pA + (kt + 1) * KC);
            fb = *reinterpret_cast<const float4*>(pB + (kt + 1) * KC);
        }

        const __half* Ah = dynsmem + cur * STAGEH;
        const __half* Al = Ah + TILEH;
        const __half* Bh = Ah + 2 * TILEH;
        const __half* Bl = Ah + 3 * TILEH;

        uint32_t af[2][4], bf[4][2], cf[4][2];
        // ---- Ah fragments + Bh fragments, main term
        #pragma unroll
        for (int mt = 0; mt < 2; ++mt) {
            const __half* ap = Ah + (arw + mt * 16) * SH + 2 * t;
            af[mt][0] = *reinterpret_cast<const uint32_t*>(ap);
            af[mt][1] = *reinterpret_cast<const uint32_t*>(ap + 8 * SH);
            af[mt][2] = *reinterpret_cast<const uint32_t*>(ap + 8);
            af[mt][3] = *reinterpret_cast<const uint32_t*>(ap + 8 * SH + 8);
        }
        #pragma unroll
        for (int nt = 0; nt < 4; ++nt) {
            const __half* bp = Bh + (bcl + nt * 8) * SH + 2 * t;
            bf[nt][0] = *reinterpret_cast<const uint32_t*>(bp);
            bf[nt][1] = *reinterpret_cast<const uint32_t*>(bp + 8);
        }
        #pragma unroll
        for (int mt = 0; mt < 2; ++mt)
            #pragma unroll
            for (int nt = 0; nt < 4; ++nt)
                mma_f16(acc[mt][nt], af[mt], bf[nt]);

        // ---- Al' fragments: corr += Al'*Bh
        uint32_t lf[2][4];
        #pragma unroll
        for (int mt = 0; mt < 2; ++mt) {
            const __half* ap = Al + (arw + mt * 16) * SH + 2 * t;
            lf[mt][0] = *reinterpret_cast<const uint32_t*>(ap);
            lf[mt][1] = *reinterpret_cast<const uint32_t*>(ap + 8 * SH);
            lf[mt][2] = *reinterpret_cast<const uint32_t*>(ap + 8);
            lf[mt][3] = *reinterpret_cast<const uint32_t*>(ap + 8 * SH + 8);
        }
        #pragma unroll
        for (int mt = 0; mt < 2; ++mt)
            #pragma unroll
            for (int nt = 0; nt < 4; ++nt)
                mma_f16(corr[mt][nt], lf[mt], bf[nt]);

        // ---- Bl' fragments: corr += Ah*Bl'
        #pragma unroll
        for (int nt = 0; nt < 4; ++nt) {
            const __half* bp = Bl + (bcl + nt * 8) * SH + 2 * t;
            cf[nt][0] = *reinterpret_cast<const uint32_t*>(bp);
            cf[nt][1] = *reinterpret_cast<const uint32_t*>(bp + 8);
        }
        #pragma unroll
        for (int mt = 0; mt < 2; ++mt)
            #pragma unroll
            for (int nt = 0; nt < 4; ++nt)
                mma_f16(corr[mt][nt], af[mt], cf[nt]);

        if (more) {
            __half* An = dynsmem + (cur ^ 1) * STAGEH;
            cvt_store(fa, An + sOff,             An + TILEH + sOff);
            cvt_store(fb, An + 2 * TILEH + sOff, An + 3 * TILEH + sOff);
        }
        __syncthreads();
        cur ^= 1;
    }

    // -------- epilogue: combine, bias/beta/sigmoid -> g_p
    const float INV2048 = 4.8828125e-4f;
    #pragma unroll
    for (int mt = 0; mt < 2; ++mt) {
        const int row = rowBase + wm * 32 + mt * 16 + g;
        #pragma unroll
        for (int nt = 0; nt < 4; ++nt) {
            const int cl  = wn * 32 + nt * 8 + 2 * t;        // block-local col
            const int col = colBase + cl;
            const float bb0 = bias_sh[cl],     bt0 = beta_sh[cl];
            const float bb1 = bias_sh[cl + 1], bt1 = beta_sh[cl + 1];
            float v0 = acc[mt][nt][0] + corr[mt][nt][0] * INV2048;
            float v1 = acc[mt][nt][1] + corr[mt][nt][1] * INV2048;
            float v2 = acc[mt][nt][2] + corr[mt][nt][2] * INV2048;
            float v3 = acc[mt][nt][3] + corr[mt][nt][3] * INV2048;
            float z0 = bt0 * (v0 + bb0);
            float z1 = bt1 * (v1 + bb1);
            float z2 = bt0 * (v2 + bb0);
            float z3 = bt1 * (v3 + bb1);
            float s0 = 1.f / (1.f + expf(-z0));
            float s1 = 1.f / (1.f + expf(-z1));
            float s2 = 1.f / (1.f + expf(-z2));
            float s3 = 1.f / (1.f + expf(-z3));
            if (col + 1 < NNODE) {
                *reinterpret_cast<float2*>(&g_p[(size_t)row * PSTR + col])       = make_float2(s0, s1);
                *reinterpret_cast<float2*>(&g_p[(size_t)(row + 8) * PSTR + col]) = make_float2(s2, s3);
            } else if (col < NNODE) {
                g_p[(size_t)row * PSTR + col]       = s0;
                g_p[(size_t)(row + 8) * PSTR + col] = s2;
            }
        }
    }
}

// ---------------- leaf softmax (Q and transposed logQ) -----------------------
__global__ void k_softmax(const float* __restrict__ lp)
{
    __shared__ float redm[4], reds[4];
    int leaf = blockIdx.x, c = threadIdx.x;    // 128 threads
    int lane = c & 31, w = c >> 5;
    float v = lp[leaf * NC + c];
    float m = v;
    #pragma unroll
    for (int off = 16; off; off >>= 1) m = fmaxf(m, __shfl_xor_sync(0xffffffffu, m, off));
    if (lane == 0) redm[w] = m;
    __syncthreads();
    m = fmaxf(fmaxf(redm[0], redm[1]), fmaxf(redm[2], redm[3]));
    float e = expf(v - m);
    float s = e;
    #pragma unroll
    for (int off = 16; off; off >>= 1) s += __shfl_xor_sync(0xffffffffu, s, off);
    if (lane == 0) reds[w] = s;
    __syncthreads();
    s = reds[0] + reds[1] + reds[2] + reds[3];
    g_Q[leaf * NC + c] = e / s;
    g_logQt[c * NLEAF + leaf] = v - m - logf(s);
}

// ---------------- path propagation / penalties / loss / argmax / output -----
#define SPB 16   // samples per block

__global__ __launch_bounds__(256)
void k_path(const int* __restrict__ target, float* __restrict__ out, int outOffset)
{
    __shared__ float bufA[SPB][257];
    __shared__ float bufB[SPB][257];
    __shared__ float s_num[128];
    __shared__ float s_den[128];
    __shared__ float s_loss;
    __shared__ int   s_leaf[SPB];

    const int tid = threadIdx.x;
    const int s0  = blockIdx.x * SPB;

    if (tid < 127) { s_num[tid] = 0.f; s_den[tid] = 0.f; }
    if (tid == 0)  s_loss = 0.f;
    if (tid < SPB) bufA[tid][0] = 1.0f;
    __syncthreads();

    for (int d = 0; d < 8; ++d) {
        const int n = 1 << d;
        const int start = n - 1;
        float (*cur)[257] = (d & 1) ? bufB : bufA;
        float (*nxt)[257] = (d & 1) ? bufA : bufB;
        const int total = SPB * n;
        for (int idx = tid; idx < total; idx += 256) {
            int s = idx >> d;
            int i = idx & (n - 1);
            float path = cur[s][i];
            float pv   = g_p[(s0 + s) * PSTR + start + i];
            if (d < 7) {
                atomicAdd(&s_num[start + i], pv * path);
                atomicAdd(&s_den[start + i], path);
            }
            nxt[s][2 * i]     = path * (1.f - pv);
            nxt[s][2 * i + 1] = path * pv;
        }
        __syncthreads();
    }

    {
        int s = tid >> 4;
        int l = tid & 15;
        int t = target[s0 + s];
        const float* lq = g_logQt + t * NLEAF;
        float lsum = 0.f;
        float bv = -1.f; int bi = 0;
        #pragma unroll
        for (int k = 0; k < 16; ++k) {
            int i = l + (k << 4);
            float pw = bufA[s][i];
            lsum += pw * lq[i];
            if (pw > bv) { bv = pw; bi = i; }
        }
        #pragma unroll
        for (int off = 8; off > 0; off >>= 1) {
            float ov = __shfl_down_sync(0xffffffffu, bv,   off, 16);
            int   oi = __shfl_down_sync(0xffffffffu, bi,   off, 16);
            float os = __shfl_down_sync(0xffffffffu, lsum, off, 16);
            lsum += os;
            if (ov > bv || (ov == bv && oi < bi)) { bv = ov; bi = oi; }
        }
        if (l == 0) {
            s_leaf[s] = bi;
            atomicAdd(&s_loss, lsum);
        }
    }
    __syncthreads();

    for (int idx = tid; idx < SPB * NC; idx += 256) {
        int s = idx >> 7;
        int c = idx & 127;
        out[outOffset + (s0 + s) * NC + c] = g_Q[s_leaf[s] * NC + c];
    }

    if (tid < 127) {
        atomicAdd(&g_pen_num[tid], s_num[tid]);
        atomicAdd(&g_pen_den[tid], s_den[tid]);
    }
    if (tid == 0) atomicAdd(&g_loss, s_loss);
}

// ---------------- finalize: total = -loss + Cpen -----------------------------
__global__ void k_final(float* __restrict__ out, int writeTotal)
{
    if (threadIdx.x != 0 || blockIdx.x != 0) return;
    float loss = g_loss / (float)BB;
    float Cpen = 0.f;
    int node = 0;
    for (int d = 0; d < 7; ++d) {
        float lam = 0.1f * exp2f(-(float)(d + 1));
        int n = 1 << d;
        float acc = 0.f;
        for (int i = 0; i < n; ++i, ++node) {
            float pen = g_pen_num[node] / g_pen_den[node];
            acc += logf(pen) + logf(1.f - pen);
        }
        Cpen -= lam * 0.5f * acc;
    }
    float total = -loss + Cpen;
    if (writeTotal) out[0] = total;
}

// ---------------- launch -----------------------------------------------------
extern "C" void kernel_launch(void* const* d_in, const int* in_sizes, int n_in,
                              void* d_out, int out_size)
{
    const float* x      = (const float*)d_in[0];
    const int*   target = (const int*)  d_in[1];
    const float* W      = (const float*)d_in[2];
    const float* bias   = (const float*)d_in[3];
    const float* beta   = (const float*)d_in[4];
    const float* leafp  = (const float*)d_in[5];
    float* out = (float*)d_out;

    int offset = out_size - BB * NC;
    if (offset < 0) offset = 0;

    cudaFuncSetAttribute(k_gemm, cudaFuncAttributeMaxDynamicSharedMemorySize, DYNSME);

    k_init<<<1, 128>>>();

    dim3 gg(2, BB / 128);   // (2 N-tiles, 64 M-tiles) = 128 CTAs
    k_gemm<<<gg, 512, DYNSME>>>(x, W, bias, beta);

    k_softmax<<<NLEAF, NC>>>(leafp);

    k_path<<<BB / SPB, 256>>>(target, out, offset);

    k_final<<<1, 32>>>(out, offset >= 1 ? 1 : 0);
}

// round 12
// speedup vs baseline: 2.2326x; 1.2389x over previous
#include <cuda_runtime.h>
#include <cuda_fp16.h>
#include <cstdint>

// Problem constants (fixed by setup_inputs)
#define BB    8192      // batch
#define DD    2048      // feature dim
#define NNODE 255       // inner nodes (2^8 - 1)
#define PSTR  256       // padded stride for p
#define NLEAF 256
#define NC    128       // classes

// ---------------- scratch (device globals; no dynamic allocation) ----------
__device__ float g_p[BB * PSTR];        // sigmoid gate per (sample, node)
__device__ float g_Q[NLEAF * NC];       // softmax(leaf_params)
__device__ float g_logQt[NC * NLEAF];   // transposed logQ: [class][leaf]
__device__ float g_pen_num[128];
__device__ float g_pen_den[128];
__device__ float g_loss;

// ---------------- init ------------------------------------------------------
__global__ void k_init() {
    int t = threadIdx.x;
    if (t < 128) { g_pen_num[t] = 0.f; g_pen_den[t] = 0.f; }
    if (t == 0) g_loss = 0.f;
}

// ================= fp16x3 tensor-core GEMM (mma.sync m16n8k16) ==============
// Split v = h + l (h = fp16 RN), store l' = l*2048 (always fp16-normal).
// acc  = Ah*Bh;  corr = Ah*Bl' + Al'*Bh;  final = acc + corr * 2^-11.
// CTA: 512 thr, 16 warps (4x4), block tile 128x128, warp tile 32x32, KC=32.
// Fragments via ldmatrix.x4; smem row stride 40 halves (conflict-free LDSM).

#define KC     32
#define NCHK   (DD / KC)            // 64
#define SH     40                   // halves per smem row (80B; LDSM conflict-free)
#define TILEB  (128 * SH * 2)       // 10240 bytes per tile array
#define STAGEB (4 * TILEB)          // Ah, Al, Bh, Bl = 40960 bytes
#define DYNSME (2 * STAGEB)         // 81920 bytes

__device__ __forceinline__ uint32_t smem_u32(const void* p) {
    uint32_t a;
    asm("{ .reg .u64 t; cvta.to.shared.u64 t, %1; cvt.u32.u64 %0, t; }"
        : "=r"(a) : "l"(p));
    return a;
}

#define LDSM4(R, addr) \
    asm volatile("ldmatrix.sync.aligned.m8n8.x4.shared.b16 {%0,%1,%2,%3}, [%4];" \
        : "=r"((R)[0]), "=r"((R)[1]), "=r"((R)[2]), "=r"((R)[3]) : "r"(addr))

__device__ __forceinline__ void mma_f16(float* c, const uint32_t* a, const uint32_t* b) {
    asm volatile(
        "mma.sync.aligned.m16n8k16.row.col.f32.f16.f16.f32 "
        "{%0,%1,%2,%3}, {%4,%5,%6,%7}, {%8,%9}, {%0,%1,%2,%3};"
        : "+f"(c[0]), "+f"(c[1]), "+f"(c[2]), "+f"(c[3])
        : "r"(a[0]), "r"(a[1]), "r"(a[2]), "r"(a[3]), "r"(b[0]), "r"(b[1]));
}

// 8 floats -> uint4 of fp16-hi and uint4 of (lo*2048) fp16
__device__ __forceinline__ void cvt8(float4 f0, float4 f1, uint4& h, uint4& l) {
    __half2 h0 = __floats2half2_rn(f0.x, f0.y);
    __half2 h1 = __floats2half2_rn(f0.z, f0.w);
    __half2 h2 = __floats2half2_rn(f1.x, f1.y);
    __half2 h3 = __floats2half2_rn(f1.z, f1.w);
    float2 g0 = __half22float2(h0), g1 = __half22float2(h1);
    float2 g2 = __half22float2(h2), g3 = __half22float2(h3);
    __half2 l0 = __floats2half2_rn((f0.x - g0.x) * 2048.f, (f0.y - g0.y) * 2048.f);
    __half2 l1 = __floats2half2_rn((f0.z - g1.x) * 2048.f, (f0.w - g1.y) * 2048.f);
    __half2 l2 = __floats2half2_rn((f1.x - g2.x) * 2048.f, (f1.y - g2.y) * 2048.f);
    __half2 l3 = __floats2half2_rn((f1.z - g3.x) * 2048.f, (f1.w - g3.y) * 2048.f);
    h.x = *reinterpret_cast<uint32_t*>(&h0);
    h.y = *reinterpret_cast<uint32_t*>(&h1);
    h.z = *reinterpret_cast<uint32_t*>(&h2);
    h.w = *reinterpret_cast<uint32_t*>(&h3);
    l.x = *reinterpret_cast<uint32_t*>(&l0);
    l.y = *reinterpret_cast<uint32_t*>(&l1);
    l.z = *reinterpret_cast<uint32_t*>(&l2);
    l.w = *reinterpret_cast<uint32_t*>(&l3);
}

__global__ __launch_bounds__(512, 1)
void k_gemm(const float* __restrict__ x, const float* __restrict__ W,
            const float* __restrict__ bias, const float* __restrict__ beta)
{
    extern __shared__ __align__(16) char dynsmem[];
    __shared__ float bias_sh[128], beta_sh[128];

    const int tid  = threadIdx.x;
    const int lane = tid & 31;
    const int wid  = tid >> 5;
    const int wm   = wid & 3;                   // warp M group (0..3)
    const int wn   = wid >> 2;                  // warp N group (0..3)
    const int rowBase = blockIdx.y * 128;
    const int colBase = blockIdx.x * 128;

    if (tid < 128) {
        int c = colBase + tid;
        bias_sh[tid] = (c < NNODE) ? bias[c] : 0.f;
        beta_sh[tid] = (c < NNODE) ? beta[c] : 0.f;
    }

    // -------- global load map: thread -> (row, 8 consecutive floats per chunk)
    const int ldRow = tid >> 2;                 // 0..127
    const int ldKf  = (tid & 3) * 8;            // float offset 0,8,16,24
    const float* pA = x + (size_t)(rowBase + ldRow) * DD + ldKf;
    int nrow = colBase + ldRow;
    if (nrow >= NNODE) nrow = 0;                // clamp; masked in epilogue
    const float* pB = W + (size_t)nrow * DD + ldKf;
    const uint32_t stOff = (uint32_t)(ldRow * SH + ldKf) * 2;  // byte off in tile

    const uint32_t smemBase = smem_u32(dynsmem);

    // -------- ldmatrix lane address bases (byte offsets within a tile array)
    const int q = lane >> 3, r = lane & 7;
    const uint32_t aOff = (uint32_t)(((wm * 32 + (q & 1) * 8 + r) * SH + (q >> 1) * 8) * 2);
    const uint32_t bOff = (uint32_t)(((wn * 32 + (q >> 1) * 8 + r) * SH + (q & 1) * 8) * 2);

    float acc[2][4][4], corr[2][4][4];
    #pragma unroll
    for (int mt = 0; mt < 2; ++mt)
        #pragma unroll
        for (int nt = 0; nt < 4; ++nt)
            #pragma unroll
            for (int qq = 0; qq < 4; ++qq) { acc[mt][nt][qq] = 0.f; corr[mt][nt][qq] = 0.f; }

    // -------- prologue: chunk 0 -> stage 0
    {
        float4 fa0 = *reinterpret_cast<const float4*>(pA);
        float4 fa1 = *reinterpret_cast<const float4*>(pA + 4);
        float4 fb0 = *reinterpret_cast<const float4*>(pB);
        float4 fb1 = *reinterpret_cast<const float4*>(pB + 4);
        uint4 h, l;
        char* st = dynsmem;
        cvt8(fa0, fa1, h, l);
        *reinterpret_cast<uint4*>(st + stOff)         = h;
        *reinterpret_cast<uint4*>(st + TILEB + stOff) = l;
        cvt8(fb0, fb1, h, l);
        *reinterpret_cast<uint4*>(st + 2 * TILEB + stOff) = h;
        *reinterpret_cast<uint4*>(st + 3 * TILEB + stOff) = l;
    }
    __syncthreads();

    int cur = 0;
    for (int kt = 0; kt < NCHK; ++kt) {
        const bool more = (kt + 1 < NCHK);
        float4 fa0, fa1, fb0, fb1;
        if (more) {
            fa0 = *reinterpret_cast<const float4*>(pA + (kt + 1) * KC);
            fa1 = *reinterpret_cast<const float4*>(pA + (kt + 1) * KC + 4);
            fb0 = *reinterpret_cast<const float4*>(pB + (kt + 1) * KC);
            fb1 = *reinterpret_cast<const float4*>(pB + (kt + 1) * KC + 4);
        }

        const uint32_t sb = smemBase + (uint32_t)cur * STAGEB;
        #pragma unroll
        for (int ksec = 0; ksec < 2; ++ksec) {
            const uint32_t ak = sb + aOff + ksec * 32;
            const uint32_t bk = sb + 2 * TILEB + bOff + ksec * 32;
            uint32_t af[2][4], lf[2][4], bfp[2][4], cfp[2][4];
            LDSM4(af[0], ak);
            LDSM4(af[1], ak + 16 * SH * 2);
            LDSM4(lf[0], ak + TILEB);
            LDSM4(lf[1], ak + TILEB + 16 * SH * 2);
            LDSM4(bfp[0], bk);
            LDSM4(bfp[1], bk + 16 * SH * 2);
            LDSM4(cfp[0], bk + TILEB);
            LDSM4(cfp[1], bk + TILEB + 16 * SH * 2);

            #pragma unroll
            for (int mt = 0; mt < 2; ++mt)
                #pragma unroll
                for (int p = 0; p < 2; ++p) {
                    mma_f16(acc[mt][2 * p],      af[mt], &bfp[p][0]);
                    mma_f16(acc[mt][2 * p + 1],  af[mt], &bfp[p][2]);
                    mma_f16(corr[mt][2 * p],     lf[mt], &bfp[p][0]);
                    mma_f16(corr[mt][2 * p + 1], lf[mt], &bfp[p][2]);
                    mma_f16(corr[mt][2 * p],     af[mt], &cfp[p][0]);
                    mma_f16(corr[mt][2 * p + 1], af[mt], &cfp[p][2]);
                }
        }

        if (more) {
            char* st = dynsmem + (cur ^ 1) * STAGEB;
            uint4 h, l;
            cvt8(fa0, fa1, h, l);
            *reinterpret_cast<uint4*>(st + stOff)         = h;
            *reinterpret_cast<uint4*>(st + TILEB + stOff) = l;
            cvt8(fb0, fb1, h, l);
            *reinterpret_cast<uint4*>(st + 2 * TILEB + stOff) = h;
            *reinterpret_cast<uint4*>(st + 3 * TILEB + stOff) = l;
        }
        __syncthreads();
        cur ^= 1;
    }

    // -------- epilogue: combine, bias/beta/sigmoid -> g_p
    const int g = lane >> 2;
    const int t = lane & 3;
    const float INV2048 = 4.8828125e-4f;
    #pragma unroll
    for (int mt = 0; mt < 2; ++mt) {
        const int row = rowBase + wm * 32 + mt * 16 + g;
        #pragma unroll
        for (int nt = 0; nt < 4; ++nt) {
            const int cl  = wn * 32 + nt * 8 + 2 * t;        // block-local col
            const int col = colBase + cl;
            const float bb0 = bias_sh[cl],     bt0 = beta_sh[cl];
            const float bb1 = bias_sh[cl + 1], bt1 = beta_sh[cl + 1];
            float v0 = acc[mt][nt][0] + corr[mt][nt][0] * INV2048;
            float v1 = acc[mt][nt][1] + corr[mt][nt][1] * INV2048;
            float v2 = acc[mt][nt][2] + corr[mt][nt][2] * INV2048;
            float v3 = acc[mt][nt][3] + corr[mt][nt][3] * INV2048;
            float z0 = bt0 * (v0 + bb0);
            float z1 = bt1 * (v1 + bb1);
            float z2 = bt0 * (v2 + bb0);
            float z3 = bt1 * (v3 + bb1);
            float s0 = 1.f / (1.f + expf(-z0));
            float s1 = 1.f / (1.f + expf(-z1));
            float s2 = 1.f / (1.f + expf(-z2));
            float s3 = 1.f / (1.f + expf(-z3));
            if (col + 1 < NNODE) {
                *reinterpret_cast<float2*>(&g_p[(size_t)row * PSTR + col])       = make_float2(s0, s1);
                *reinterpret_cast<float2*>(&g_p[(size_t)(row + 8) * PSTR + col]) = make_float2(s2, s3);
            } else if (col < NNODE) {
                g_p[(size_t)row * PSTR + col]       = s0;
                g_p[(size_t)(row + 8) * PSTR + col] = s2;
            }
        }
    }
}

// ---------------- leaf softmax (Q and transposed logQ) -----------------------
__global__ void k_softmax(const float* __restrict__ lp)
{
    __shared__ float redm[4], reds[4];
    int leaf = blockIdx.x, c = threadIdx.x;    // 128 threads
    int lane = c & 31, w = c >> 5;
    float v = lp[leaf * NC + c];
    float m = v;
    #pragma unroll
    for (int off = 16; off; off >>= 1) m = fmaxf(m, __shfl_xor_sync(0xffffffffu, m, off));
    if (lane == 0) redm[w] = m;
    __syncthreads();
    m = fmaxf(fmaxf(redm[0], redm[1]), fmaxf(redm[2], redm[3]));
    float e = expf(v - m);
    float s = e;
    #pragma unroll
    for (int off = 16; off; off >>= 1) s += __shfl_xor_sync(0xffffffffu, s, off);
    if (lane == 0) reds[w] = s;
    __syncthreads();
    s = reds[0] + reds[1] + reds[2] + reds[3];
    g_Q[leaf * NC + c] = e / s;
    g_logQt[c * NLEAF + leaf] = v - m - logf(s);
}

// ---------------- path propagation / penalties / loss / argmax / output -----
#define SPB 16   // samples per block

__global__ __launch_bounds__(256)
void k_path(const int* __restrict__ target, float* __restrict__ out, int outOffset)
{
    __shared__ float bufA[SPB][257];
    __shared__ float bufB[SPB][257];
    __shared__ float s_num[128];
    __shared__ float s_den[128];
    __shared__ float s_loss;
    __shared__ int   s_leaf[SPB];

    const int tid = threadIdx.x;
    const int s0  = blockIdx.x * SPB;

    if (tid < 127) { s_num[tid] = 0.f; s_den[tid] = 0.f; }
    if (tid == 0)  s_loss = 0.f;
    if (tid < SPB) bufA[tid][0] = 1.0f;
    __syncthreads();

    for (int d = 0; d < 8; ++d) {
        const int n = 1 << d;
        const int start = n - 1;
        float (*cur)[257] = (d & 1) ? bufB : bufA;
        float (*nxt)[257] = (d & 1) ? bufA : bufB;
        const int total = SPB * n;
        for (int idx = tid; idx < total; idx += 256) {
            int s = idx >> d;
            int i = idx & (n - 1);
            float path = cur[s][i];
            float pv   = g_p[(s0 + s) * PSTR + start + i];
            if (d < 7) {
                atomicAdd(&s_num[start + i], pv * path);
                atomicAdd(&s_den[start + i], path);
            }
            nxt[s][2 * i]     = path * (1.f - pv);
            nxt[s][2 * i + 1] = path * pv;
        }
        __syncthreads();
    }

    {
        int s = tid >> 4;
        int l = tid & 15;
        int t = target[s0 + s];
        const float* lq = g_logQt + t * NLEAF;
        float lsum = 0.f;
        float bv = -1.f; int bi = 0;
        #pragma unroll
        for (int k = 0; k < 16; ++k) {
            int i = l + (k << 4);
            float pw = bufA[s][i];
            lsum += pw * lq[i];
            if (pw > bv) { bv = pw; bi = i; }
        }
        #pragma unroll
        for (int off = 8; off > 0; off >>= 1) {
            float ov = __shfl_down_sync(0xffffffffu, bv,   off, 16);
            int   oi = __shfl_down_sync(0xffffffffu, bi,   off, 16);
            float os = __shfl_down_sync(0xffffffffu, lsum, off, 16);
            lsum += os;
            if (ov > bv || (ov == bv && oi < bi)) { bv = ov; bi = oi; }
        }
        if (l == 0) {
            s_leaf[s] = bi;
            atomicAdd(&s_loss, lsum);
        }
    }
    __syncthreads();

    for (int idx = tid; idx < SPB * NC; idx += 256) {
        int s = idx >> 7;
        int c = idx & 127;
        out[outOffset + (s0 + s) * NC + c] = g_Q[s_leaf[s] * NC + c];
    }

    if (tid < 127) {
        atomicAdd(&g_pen_num[tid], s_num[tid]);
        atomicAdd(&g_pen_den[tid], s_den[tid]);
    }
    if (tid == 0) atomicAdd(&g_loss, s_loss);
}

// ---------------- finalize: total = -loss + Cpen -----------------------------
__global__ void k_final(float* __restrict__ out, int writeTotal)
{
    if (threadIdx.x != 0 || blockIdx.x != 0) return;
    float loss = g_loss / (float)BB;
    float Cpen = 0.f;
    int node = 0;
    for (int d = 0; d < 7; ++d) {
        float lam = 0.1f * exp2f(-(float)(d + 1));
        int n = 1 << d;
        float acc = 0.f;
        for (int i = 0; i < n; ++i, ++node) {
            float pen = g_pen_num[node] / g_pen_den[node];
            acc += logf(pen) + logf(1.f - pen);
        }
        Cpen -= lam * 0.5f * acc;
    }
    float total = -loss + Cpen;
    if (writeTotal) out[0] = total;
}

// ---------------- launch -----------------------------------------------------
extern "C" void kernel_launch(void* const* d_in, const int* in_sizes, int n_in,
                              void* d_out, int out_size)
{
    const float* x      = (const float*)d_in[0];
    const int*   target = (const int*)  d_in[1];
    const float* W      = (const float*)d_in[2];
    const float* bias   = (const float*)d_in[3];
    const float* beta   = (const float*)d_in[4];
    const float* leafp  = (const float*)d_in[5];
    float* out = (float*)d_out;

    int offset = out_size - BB * NC;
    if (offset < 0) offset = 0;

    cudaFuncSetAttribute(k_gemm, cudaFuncAttributeMaxDynamicSharedMemorySize, DYNSME);

    k_init<<<1, 128>>>();

    dim3 gg(2, BB / 128);   // (2 N-tiles, 64 M-tiles) = 128 CTAs
    k_gemm<<<gg, 512, DYNSME>>>(x, W, bias, beta);

    k_softmax<<<NLEAF, NC>>>(leafp);

    k_path<<<BB / SPB, 256>>>(target, out, offset);

    k_final<<<1, 32>>>(out, offset >= 1 ? 1 : 0);
}

// round 14
// speedup vs baseline: 2.6550x; 1.1892x over previous
#include <cuda_runtime.h>
#include <cuda_fp16.h>
#include <cstdint>

// Problem constants (fixed by setup_inputs)
#define BB    8192      // batch
#define DD    2048      // feature dim
#define NNODE 255       // inner nodes (2^8 - 1)
#define PSTR  256       // padded stride for p
#define NLEAF 256
#define NC    128       // classes

// ---------------- scratch (device globals; no dynamic allocation) ----------
__device__ float g_p[BB * PSTR];        // sigmoid gate per (sample, node)
__device__ float g_Q[NLEAF * NC];       // softmax(leaf_params)
__device__ float g_logQt[NC * NLEAF];   // transposed logQ: [class][leaf]
__device__ float g_pen_num[128];
__device__ float g_pen_den[128];
__device__ float g_loss;
__device__ unsigned g_done;             // ticket for fused finalize

// ---------------- init ------------------------------------------------------
__global__ void k_init() {
    int t = threadIdx.x;
    if (t < 128) { g_pen_num[t] = 0.f; g_pen_den[t] = 0.f; }
    if (t == 0) { g_loss = 0.f; g_done = 0u; }
}

// ================= fp16x3 tensor-core GEMM (mma.sync m16n8k16) ==============
// Split v = h + l (h = fp16 RN), store l' = l*2048 (always fp16-normal).
// acc  = Ah*Bh;  corr = Ah*Bl' + Al'*Bh;  final = acc + corr * 2^-11.
// CTA: 512 thr, 16 warps (4x4), block tile 128x128, warp tile 32x32, KC=32.
// Fragments via ldmatrix.x4; smem row stride 40 halves (conflict-free LDSM).

#define KC     32
#define NCHK   (DD / KC)            // 64
#define SH     40                   // halves per smem row (80B; LDSM conflict-free)
#define TILEB  (128 * SH * 2)       // 10240 bytes per tile array
#define STAGEB (4 * TILEB)          // Ah, Al, Bh, Bl = 40960 bytes
#define DYNSME (2 * STAGEB)         // 81920 bytes

__device__ __forceinline__ uint32_t smem_u32(const void* p) {
    uint32_t a;
    asm("{ .reg .u64 t; cvta.to.shared.u64 t, %1; cvt.u32.u64 %0, t; }"
        : "=r"(a) : "l"(p));
    return a;
}

#define LDSM4(R, addr) \
    asm volatile("ldmatrix.sync.aligned.m8n8.x4.shared.b16 {%0,%1,%2,%3}, [%4];" \
        : "=r"((R)[0]), "=r"((R)[1]), "=r"((R)[2]), "=r"((R)[3]) : "r"(addr))

__device__ __forceinline__ void mma_f16(float* c, const uint32_t* a, const uint32_t* b) {
    asm volatile(
        "mma.sync.aligned.m16n8k16.row.col.f32.f16.f16.f32 "
        "{%0,%1,%2,%3}, {%4,%5,%6,%7}, {%8,%9}, {%0,%1,%2,%3};"
        : "+f"(c[0]), "+f"(c[1]), "+f"(c[2]), "+f"(c[3])
        : "r"(a[0]), "r"(a[1]), "r"(a[2]), "r"(a[3]), "r"(b[0]), "r"(b[1]));
}

// 8 floats -> uint4 of fp16-hi and uint4 of (lo*2048) fp16
__device__ __forceinline__ void cvt8(float4 f0, float4 f1, uint4& h, uint4& l) {
    __half2 h0 = __floats2half2_rn(f0.x, f0.y);
    __half2 h1 = __floats2half2_rn(f0.z, f0.w);
    __half2 h2 = __floats2half2_rn(f1.x, f1.y);
    __half2 h3 = __floats2half2_rn(f1.z, f1.w);
    float2 g0 = __half22float2(h0), g1 = __half22float2(h1);
    float2 g2 = __half22float2(h2), g3 = __half22float2(h3);
    __half2 l0 = __floats2half2_rn((f0.x - g0.x) * 2048.f, (f0.y - g0.y) * 2048.f);
    __half2 l1 = __floats2half2_rn((f0.z - g1.x) * 2048.f, (f0.w - g1.y) * 2048.f);
    __half2 l2 = __floats2half2_rn((f1.x - g2.x) * 2048.f, (f1.y - g2.y) * 2048.f);
    __half2 l3 = __floats2half2_rn((f1.z - g3.x) * 2048.f, (f1.w - g3.y) * 2048.f);
    h.x = *reinterpret_cast<uint32_t*>(&h0);
    h.y = *reinterpret_cast<uint32_t*>(&h1);
    h.z = *reinterpret_cast<uint32_t*>(&h2);
    h.w = *reinterpret_cast<uint32_t*>(&h3);
    l.x = *reinterpret_cast<uint32_t*>(&l0);
    l.y = *reinterpret_cast<uint32_t*>(&l1);
    l.z = *reinterpret_cast<uint32_t*>(&l2);
    l.w = *reinterpret_cast<uint32_t*>(&l3);
}

__global__ __launch_bounds__(512, 1)
void k_gemm(const float* __restrict__ x, const float* __restrict__ W,
            const float* __restrict__ bias, const float* __restrict__ beta)
{
    extern __shared__ __align__(16) char dynsmem[];
    __shared__ float bias_sh[128], beta_sh[128];

    const int tid  = threadIdx.x;
    const int lane = tid & 31;
    const int wid  = tid >> 5;
    const int wm   = wid & 3;                   // warp M group (0..3)
    const int wn   = wid >> 2;                  // warp N group (0..3)
    const int rowBase = blockIdx.y * 128;
    const int colBase = blockIdx.x * 128;

    if (tid < 128) {
        int c = colBase + tid;
        bias_sh[tid] = (c < NNODE) ? bias[c] : 0.f;
        beta_sh[tid] = (c < NNODE) ? beta[c] : 0.f;
    }

    // -------- global load map: thread -> (row, 8 consecutive floats per chunk)
    const int ldRow = tid >> 2;                 // 0..127
    const int ldKf  = (tid & 3) * 8;            // float offset 0,8,16,24
    const float* pA = x + (size_t)(rowBase + ldRow) * DD + ldKf;
    int nrow = colBase + ldRow;
    if (nrow >= NNODE) nrow = 0;                // clamp; masked in epilogue
    const float* pB = W + (size_t)nrow * DD + ldKf;
    const uint32_t stOff = (uint32_t)(ldRow * SH + ldKf) * 2;  // byte off in tile

    const uint32_t smemBase = smem_u32(dynsmem);

    // -------- ldmatrix lane address bases (byte offsets within a tile array)
    const int q = lane >> 3, r = lane & 7;
    const uint32_t aOff = (uint32_t)(((wm * 32 + (q & 1) * 8 + r) * SH + (q >> 1) * 8) * 2);
    const uint32_t bOff = (uint32_t)(((wn * 32 + (q >> 1) * 8 + r) * SH + (q & 1) * 8) * 2);

    float acc[2][4][4], corr[2][4][4];
    #pragma unroll
    for (int mt = 0; mt < 2; ++mt)
        #pragma unroll
        for (int nt = 0; nt < 4; ++nt)
            #pragma unroll
            for (int qq = 0; qq < 4; ++qq) { acc[mt][nt][qq] = 0.f; corr[mt][nt][qq] = 0.f; }

    // -------- prologue: chunk 0 -> stage 0
    {
        float4 fa0 = *reinterpret_cast<const float4*>(pA);
        float4 fa1 = *reinterpret_cast<const float4*>(pA + 4);
        float4 fb0 = *reinterpret_cast<const float4*>(pB);
        float4 fb1 = *reinterpret_cast<const float4*>(pB + 4);
        uint4 h, l;
        char* st = dynsmem;
        cvt8(fa0, fa1, h, l);
        *reinterpret_cast<uint4*>(st + stOff)         = h;
        *reinterpret_cast<uint4*>(st + TILEB + stOff) = l;
        cvt8(fb0, fb1, h, l);
        *reinterpret_cast<uint4*>(st + 2 * TILEB + stOff) = h;
        *reinterpret_cast<uint4*>(st + 3 * TILEB + stOff) = l;
    }
    __syncthreads();

    int cur = 0;
    for (int kt = 0; kt < NCHK; ++kt) {
        const bool more = (kt + 1 < NCHK);
        float4 fa0, fa1, fb0, fb1;
        if (more) {
            fa0 = *reinterpret_cast<const float4*>(pA + (kt + 1) * KC);
            fa1 = *reinterpret_cast<const float4*>(pA + (kt + 1) * KC + 4);
            fb0 = *reinterpret_cast<const float4*>(pB + (kt + 1) * KC);
            fb1 = *reinterpret_cast<const float4*>(pB + (kt + 1) * KC + 4);
        }

        const uint32_t sb = smemBase + (uint32_t)cur * STAGEB;
        #pragma unroll
        for (int ksec = 0; ksec < 2; ++ksec) {
            const uint32_t ak = sb + aOff + ksec * 32;
            const uint32_t bk = sb + 2 * TILEB + bOff + ksec * 32;
            uint32_t af[2][4], lf[2][4], bfp[2][4], cfp[2][4];
            LDSM4(af[0], ak);
            LDSM4(af[1], ak + 16 * SH * 2);
            LDSM4(lf[0], ak + TILEB);
            LDSM4(lf[1], ak + TILEB + 16 * SH * 2);
            LDSM4(bfp[0], bk);
            LDSM4(bfp[1], bk + 16 * SH * 2);
            LDSM4(cfp[0], bk + TILEB);
            LDSM4(cfp[1], bk + TILEB + 16 * SH * 2);

            #pragma unroll
            for (int mt = 0; mt < 2; ++mt)
                #pragma unroll
                for (int p = 0; p < 2; ++p) {
                    mma_f16(acc[mt][2 * p],      af[mt], &bfp[p][0]);
                    mma_f16(acc[mt][2 * p + 1],  af[mt], &bfp[p][2]);
                    mma_f16(corr[mt][2 * p],     lf[mt], &bfp[p][0]);
                    mma_f16(corr[mt][2 * p + 1], lf[mt], &bfp[p][2]);
                    mma_f16(corr[mt][2 * p],     af[mt], &cfp[p][0]);
                    mma_f16(corr[mt][2 * p + 1], af[mt], &cfp[p][2]);
                }
        }

        if (more) {
            char* st = dynsmem + (cur ^ 1) * STAGEB;
            uint4 h, l;
            cvt8(fa0, fa1, h, l);
            *reinterpret_cast<uint4*>(st + stOff)         = h;
            *reinterpret_cast<uint4*>(st + TILEB + stOff) = l;
            cvt8(fb0, fb1, h, l);
            *reinterpret_cast<uint4*>(st + 2 * TILEB + stOff) = h;
            *reinterpret_cast<uint4*>(st + 3 * TILEB + stOff) = l;
        }
        __syncthreads();
        cur ^= 1;
    }

    // -------- epilogue: combine, bias/beta/sigmoid -> g_p
    const int g = lane >> 2;
    const int t = lane & 3;
    const float INV2048 = 4.8828125e-4f;
    #pragma unroll
    for (int mt = 0; mt < 2; ++mt) {
        const int row = rowBase + wm * 32 + mt * 16 + g;
        #pragma unroll
        for (int nt = 0; nt < 4; ++nt) {
            const int cl  = wn * 32 + nt * 8 + 2 * t;        // block-local col
            const int col = colBase + cl;
            const float bb0 = bias_sh[cl],     bt0 = beta_sh[cl];
            const float bb1 = bias_sh[cl + 1], bt1 = beta_sh[cl + 1];
            float v0 = acc[mt][nt][0] + corr[mt][nt][0] * INV2048;
            float v1 = acc[mt][nt][1] + corr[mt][nt][1] * INV2048;
            float v2 = acc[mt][nt][2] + corr[mt][nt][2] * INV2048;
            float v3 = acc[mt][nt][3] + corr[mt][nt][3] * INV2048;
            float z0 = bt0 * (v0 + bb0);
            float z1 = bt1 * (v1 + bb1);
            float z2 = bt0 * (v2 + bb0);
            float z3 = bt1 * (v3 + bb1);
            float s0 = 1.f / (1.f + expf(-z0));
            float s1 = 1.f / (1.f + expf(-z1));
            float s2 = 1.f / (1.f + expf(-z2));
            float s3 = 1.f / (1.f + expf(-z3));
            if (col + 1 < NNODE) {
                *reinterpret_cast<float2*>(&g_p[(size_t)row * PSTR + col])       = make_float2(s0, s1);
                *reinterpret_cast<float2*>(&g_p[(size_t)(row + 8) * PSTR + col]) = make_float2(s2, s3);
            } else if (col < NNODE) {
                g_p[(size_t)row * PSTR + col]       = s0;
                g_p[(size_t)(row + 8) * PSTR + col] = s2;
            }
        }
    }
}

// ---------------- leaf softmax (Q and transposed logQ) -----------------------
__global__ void k_softmax(const float* __restrict__ lp)
{
    __shared__ float redm[4], reds[4];
    int leaf = blockIdx.x, c = threadIdx.x;    // 128 threads
    int lane = c & 31, w = c >> 5;
    float v = lp[leaf * NC + c];
    float m = v;
    #pragma unroll
    for (int off = 16; off; off >>= 1) m = fmaxf(m, __shfl_xor_sync(0xffffffffu, m, off));
    if (lane == 0) redm[w] = m;
    __syncthreads();
    m = fmaxf(fmaxf(redm[0], redm[1]), fmaxf(redm[2], redm[3]));
    float e = expf(v - m);
    float s = e;
    #pragma unroll
    for (int off = 16; off; off >>= 1) s += __shfl_xor_sync(0xffffffffu, s, off);
    if (lane == 0) reds[w] = s;
    __syncthreads();
    s = reds[0] + reds[1] + reds[2] + reds[3];
    g_Q[leaf * NC + c] = e / s;
    g_logQt[c * NLEAF + leaf] = v - m - logf(s);
}

// ======== path: warp-per-sample register tree + fused finalize ==============
// Lanes <-> 32 depth-5 nodes. Depths 0..4 propagate via shuffles from p[0..30];
// depths 5..7 gates are direct per-lane loads. Penalties accumulate via
// predicated multi-lane smem atomics; loss/argmax via warp reduction.
// NOTE: output rows start at out+1 (4B-aligned only) -> scalar stores.
__global__ __launch_bounds__(256)
void k_path(const int* __restrict__ target, float* __restrict__ out, int outOffset)
{
    __shared__ float s_num[128];
    __shared__ float s_den[128];
    __shared__ float s_loss;
    __shared__ unsigned s_rank;
    __shared__ float s_red[128];

    const int tid  = threadIdx.x;
    const int lane = tid & 31;
    const int wid  = tid >> 5;
    const int s    = blockIdx.x * 8 + wid;      // one sample per warp
    const unsigned FULL = 0xffffffffu;

    if (tid < 128) { s_num[tid] = 0.f; s_den[tid] = 0.f; }
    if (tid == 0)  s_loss = 0.f;
    __syncthreads();

    const float* pr = g_p + (size_t)s * PSTR;
    // gate loads: lane l owns depth-5 node 31+l and its subtree
    float pS  = pr[lane];                 // nodes 0..30 (lane 31 unused)
    float p5  = pr[31 + lane];            // depth-5 gate
    float g60 = pr[63 + 2 * lane];        // depth-6 gates
    float g61 = pr[64 + 2 * lane];
    float g70 = pr[127 + 4 * lane];       // depth-7 gates
    float g71 = pr[128 + 4 * lane];
    float g72 = pr[129 + 4 * lane];
    float g73 = pr[130 + 4 * lane];

    // depths 0..4: lane j (< 2^d) holds path to node (2^d-1)+j
    float path = 1.f;
    #pragma unroll
    for (int d = 0; d < 5; ++d) {
        const int w = 1 << d;
        const int n = (w - 1) + lane;                       // my node index
        float pv = __shfl_sync(FULL, pS, n & 31);
        if (lane < w) {
            atomicAdd(&s_num[n], pv * path);
            atomicAdd(&s_den[n], path);
        }
        float pp = __shfl_sync(FULL, path, lane >> 1);
        float pg = __shfl_sync(FULL, pS, ((w - 1) + (lane >> 1)) & 31);
        float f  = (lane & 1) ? pg : (1.f - pg);
        float np = pp * f;
        if (lane < 2 * w) path = np;
    }
    // path = path to depth-5 node 31+lane (all 32 lanes valid)
    atomicAdd(&s_num[31 + lane], p5 * path);
    atomicAdd(&s_den[31 + lane], path);
    float c0 = path * (1.f - p5);
    float c1 = path * p5;
    // depth-6 nodes 63+2l, 64+2l
    atomicAdd(&s_num[63 + 2 * lane], g60 * c0);
    atomicAdd(&s_den[63 + 2 * lane], c0);
    atomicAdd(&s_num[64 + 2 * lane], g61 * c1);
    atomicAdd(&s_den[64 + 2 * lane], c1);
    float e0 = c0 * (1.f - g60), e1 = c0 * g60;
    float e2 = c1 * (1.f - g61), e3 = c1 * g61;
    // leaves 8*lane .. 8*lane+7
    float L[8];
    L[0] = e0 * (1.f - g70); L[1] = e0 * g70;
    L[2] = e1 * (1.f - g71); L[3] = e1 * g71;
    L[4] = e2 * (1.f - g72); L[5] = e2 * g72;
    L[6] = e3 * (1.f - g73); L[7] = e3 * g73;

    // loss + argmax
    const int t = target[s];
    const float* lq = g_logQt + (size_t)t * NLEAF + 8 * lane;
    float4 q0 = *reinterpret_cast<const float4*>(lq);
    float4 q1 = *reinterpret_cast<const float4*>(lq + 4);
    float lsum = L[0] * q0.x + L[1] * q0.y + L[2] * q0.z + L[3] * q0.w
               + L[4] * q1.x + L[5] * q1.y + L[6] * q1.z + L[7] * q1.w;
    float bv = L[0]; int bi = 8 * lane;
    #pragma unroll
    for (int k = 1; k < 8; ++k)
        if (L[k] > bv) { bv = L[k]; bi = 8 * lane + k; }   // strict: first max
    #pragma unroll
    for (int off = 16; off; off >>= 1) {
        float ov = __shfl_down_sync(FULL, bv, off);
        int   oi = __shfl_down_sync(FULL, bi, off);
        float os = __shfl_down_sync(FULL, lsum, off);
        lsum += os;
        if (ov > bv || (ov == bv && oi < bi)) { bv = ov; bi = oi; }
    }
    bi = __shfl_sync(FULL, bi, 0);
    if (lane == 0) atomicAdd(&s_loss, lsum);

    // output row: out[s] = Q[leaf]  (dst is only 4B-aligned -> scalar stores)
    {
        const float4* qrow = reinterpret_cast<const float4*>(g_Q + (size_t)bi * NC);
        float4 qv = qrow[lane];
        float* orow = out + outOffset + (size_t)s * NC + 4 * lane;
        orow[0] = qv.x;
        orow[1] = qv.y;
        orow[2] = qv.z;
        orow[3] = qv.w;
    }

    __syncthreads();
    if (tid < 127) {
        atomicAdd(&g_pen_num[tid], s_num[tid]);
        atomicAdd(&g_pen_den[tid], s_den[tid]);
    }
    if (tid == 0) atomicAdd(&g_loss, s_loss);

    // -------- fused finalize: last block computes total -> out[0]
    __threadfence();
    if (tid == 0) s_rank = atomicAdd(&g_done, 1u);
    __syncthreads();
    if (s_rank == gridDim.x - 1) {
        float v = 0.f;
        if (tid < 127) {
            float num = *((volatile float*)&g_pen_num[tid]);
            float den = *((volatile float*)&g_pen_den[tid]);
            float pen = num / den;
            int dd = 31 - __clz(tid + 1);                 // depth of node tid
            float lam = 0.1f * exp2f(-(float)(dd + 1));
            v = -lam * 0.5f * (logf(pen) + logf(1.f - pen));
        }
        if (tid < 128) s_red[tid] = v;
        __syncthreads();
        if (tid == 0) {
            float Cpen = 0.f;
            for (int i = 0; i < 127; ++i) Cpen += s_red[i];
            float loss = (*((volatile float*)&g_loss)) / (float)BB;
            if (outOffset >= 1) out[0] = -loss + Cpen;
        }
    }
}

// ---------------- launch -----------------------------------------------------
extern "C" void kernel_launch(void* const* d_in, const int* in_sizes, int n_in,
                              void* d_out, int out_size)
{
    const float* x      = (const float*)d_in[0];
    const int*   target = (const int*)  d_in[1];
    const float* W      = (const float*)d_in[2];
    const float* bias   = (const float*)d_in[3];
    const float* beta   = (const float*)d_in[4];
    const float* leafp  = (const float*)d_in[5];
    float* out = (float*)d_out;

    int offset = out_size - BB * NC;
    if (offset < 0) offset = 0;

    cudaFuncSetAttribute(k_gemm, cudaFuncAttributeMaxDynamicSharedMemorySize, DYNSME);

    k_init<<<1, 128>>>();

    dim3 gg(2, BB / 128);   // (2 N-tiles, 64 M-tiles) = 128 CTAs
    k_gemm<<<gg, 512, DYNSME>>>(x, W, bias, beta);

    k_softmax<<<NLEAF, NC>>>(leafp);

    k_path<<<BB / 8, 256>>>(target, out, offset);   // 1024 blocks, warp/sample
}

// round 16
// speedup vs baseline: 2.7803x; 1.0472x over previous
#include <cuda_runtime.h>
#include <cuda_fp16.h>
#include <cstdint>

// Problem constants (fixed by setup_inputs)
#define BB    8192      // batch
#define DD    2048      // feature dim
#define NNODE 255       // inner nodes (2^8 - 1)
#define PSTR  256       // padded stride for p
#define NLEAF 256
#define NC    128       // classes

// ---------------- scratch (device globals; no dynamic allocation) ----------
__device__ float g_p[BB * PSTR];        // sigmoid gate per (sample, node)
__device__ float g_Q[NLEAF * NC];       // softmax(leaf_params)
__device__ float g_logQt[NC * NLEAF];   // transposed logQ: [class][leaf]
__device__ float g_pen_num[128];
__device__ float g_pen_den[128];
__device__ float g_loss;
__device__ unsigned g_done;             // ticket for fused finalize

// ---------------- init ------------------------------------------------------
__global__ void k_init() {
    int t = threadIdx.x;
    if (t < 128) { g_pen_num[t] = 0.f; g_pen_den[t] = 0.f; }
    if (t == 0) { g_loss = 0.f; g_done = 0u; }
}

// ================= fp16x3 tensor-core GEMM (mma.sync m16n8k16) ==============
// Split v = h + l (h = fp16 RN), store l' = l*2048 (always fp16-normal).
// acc  = Ah*Bh;  corr = Ah*Bl' + Al'*Bh;  final = acc + corr * 2^-11.
// CTA: 512 thr, 16 warps (4x4), block tile 128x128, warp tile 32x32, KC=32.
// Fragments via ldmatrix.x4; smem row stride 40 halves (conflict-free LDSM).

#define KC     32
#define NCHK   (DD / KC)            // 64
#define SH     40                   // halves per smem row (80B; LDSM conflict-free)
#define TILEB  (128 * SH * 2)       // 10240 bytes per tile array
#define STAGEB (4 * TILEB)          // Ah, Al, Bh, Bl = 40960 bytes
#define DYNSME (2 * STAGEB)         // 81920 bytes

__device__ __forceinline__ uint32_t smem_u32(const void* p) {
    uint32_t a;
    asm("{ .reg .u64 t; cvta.to.shared.u64 t, %1; cvt.u32.u64 %0, t; }"
        : "=r"(a) : "l"(p));
    return a;
}

#define LDSM4(R, addr) \
    asm volatile("ldmatrix.sync.aligned.m8n8.x4.shared.b16 {%0,%1,%2,%3}, [%4];" \
        : "=r"((R)[0]), "=r"((R)[1]), "=r"((R)[2]), "=r"((R)[3]) : "r"(addr))

__device__ __forceinline__ void mma_f16(float* c, const uint32_t* a, const uint32_t* b) {
    asm volatile(
        "mma.sync.aligned.m16n8k16.row.col.f32.f16.f16.f32 "
        "{%0,%1,%2,%3}, {%4,%5,%6,%7}, {%8,%9}, {%0,%1,%2,%3};"
        : "+f"(c[0]), "+f"(c[1]), "+f"(c[2]), "+f"(c[3])
        : "r"(a[0]), "r"(a[1]), "r"(a[2]), "r"(a[3]), "r"(b[0]), "r"(b[1]));
}

// 8 floats -> uint4 of fp16-hi and uint4 of (lo*2048) fp16
__device__ __forceinline__ void cvt8(float4 f0, float4 f1, uint4& h, uint4& l) {
    __half2 h0 = __floats2half2_rn(f0.x, f0.y);
    __half2 h1 = __floats2half2_rn(f0.z, f0.w);
    __half2 h2 = __floats2half2_rn(f1.x, f1.y);
    __half2 h3 = __floats2half2_rn(f1.z, f1.w);
    float2 g0 = __half22float2(h0), g1 = __half22float2(h1);
    float2 g2 = __half22float2(h2), g3 = __half22float2(h3);
    __half2 l0 = __floats2half2_rn((f0.x - g0.x) * 2048.f, (f0.y - g0.y) * 2048.f);
    __half2 l1 = __floats2half2_rn((f0.z - g1.x) * 2048.f, (f0.w - g1.y) * 2048.f);
    __half2 l2 = __floats2half2_rn((f1.x - g2.x) * 2048.f, (f1.y - g2.y) * 2048.f);
    __half2 l3 = __floats2half2_rn((f1.z - g3.x) * 2048.f, (f1.w - g3.y) * 2048.f);
    h.x = *reinterpret_cast<uint32_t*>(&h0);
    h.y = *reinterpret_cast<uint32_t*>(&h1);
    h.z = *reinterpret_cast<uint32_t*>(&h2);
    h.w = *reinterpret_cast<uint32_t*>(&h3);
    l.x = *reinterpret_cast<uint32_t*>(&l0);
    l.y = *reinterpret_cast<uint32_t*>(&l1);
    l.z = *reinterpret_cast<uint32_t*>(&l2);
    l.w = *reinterpret_cast<uint32_t*>(&l3);
}

__global__ __launch_bounds__(512, 1)
void k_gemm(const float* __restrict__ x, const float* __restrict__ W,
            const float* __restrict__ bias, const float* __restrict__ beta)
{
    extern __shared__ __align__(16) char dynsmem[];
    __shared__ float bias_sh[128], beta_sh[128];

    const int tid  = threadIdx.x;
    const int lane = tid & 31;
    const int wid  = tid >> 5;
    const int wm   = wid & 3;                   // warp M group (0..3)
    const int wn   = wid >> 2;                  // warp N group (0..3)
    const int rowBase = blockIdx.y * 128;
    const int colBase = blockIdx.x * 128;

    if (tid < 128) {
        int c = colBase + tid;
        bias_sh[tid] = (c < NNODE) ? bias[c] : 0.f;
        beta_sh[tid] = (c < NNODE) ? beta[c] : 0.f;
    }

    // -------- global load map: thread -> (row, 8 consecutive floats per chunk)
    const int ldRow = tid >> 2;                 // 0..127
    const int ldKf  = (tid & 3) * 8;            // float offset 0,8,16,24
    const float* pA = x + (size_t)(rowBase + ldRow) * DD + ldKf;
    int nrow = colBase + ldRow;
    if (nrow >= NNODE) nrow = 0;                // clamp; masked in epilogue
    const float* pB = W + (size_t)nrow * DD + ldKf;
    const uint32_t stOff = (uint32_t)(ldRow * SH + ldKf) * 2;  // byte off in tile

    const uint32_t smemBase = smem_u32(dynsmem);

    // -------- ldmatrix lane address bases (byte offsets within a tile array)
    const int q = lane >> 3, r = lane & 7;
    const uint32_t aOff = (uint32_t)(((wm * 32 + (q & 1) * 8 + r) * SH + (q >> 1) * 8) * 2);
    const uint32_t bOff = (uint32_t)(((wn * 32 + (q >> 1) * 8 + r) * SH + (q & 1) * 8) * 2);

    float acc[2][4][4], corr[2][4][4];
    #pragma unroll
    for (int mt = 0; mt < 2; ++mt)
        #pragma unroll
        for (int nt = 0; nt < 4; ++nt)
            #pragma unroll
            for (int qq = 0; qq < 4; ++qq) { acc[mt][nt][qq] = 0.f; corr[mt][nt][qq] = 0.f; }

    // -------- prologue: chunk 0 -> stage 0
    {
        float4 fa0 = *reinterpret_cast<const float4*>(pA);
        float4 fa1 = *reinterpret_cast<const float4*>(pA + 4);
        float4 fb0 = *reinterpret_cast<const float4*>(pB);
        float4 fb1 = *reinterpret_cast<const float4*>(pB + 4);
        uint4 h, l;
        char* st = dynsmem;
        cvt8(fa0, fa1, h, l);
        *reinterpret_cast<uint4*>(st + stOff)         = h;
        *reinterpret_cast<uint4*>(st + TILEB + stOff) = l;
        cvt8(fb0, fb1, h, l);
        *reinterpret_cast<uint4*>(st + 2 * TILEB + stOff) = h;
        *reinterpret_cast<uint4*>(st + 3 * TILEB + stOff) = l;
    }
    __syncthreads();

    int cur = 0;
    for (int kt = 0; kt < NCHK; ++kt) {
        const bool more = (kt + 1 < NCHK);
        float4 fa0, fa1, fb0, fb1;
        if (more) {
            fa0 = *reinterpret_cast<const float4*>(pA + (kt + 1) * KC);
            fa1 = *reinterpret_cast<const float4*>(pA + (kt + 1) * KC + 4);
            fb0 = *reinterpret_cast<const float4*>(pB + (kt + 1) * KC);
            fb1 = *reinterpret_cast<const float4*>(pB + (kt + 1) * KC + 4);
        }

        const uint32_t sb = smemBase + (uint32_t)cur * STAGEB;
        #pragma unroll
        for (int ksec = 0; ksec < 2; ++ksec) {
            const uint32_t ak = sb + aOff + ksec * 32;
            const uint32_t bk = sb + 2 * TILEB + bOff + ksec * 32;
            uint32_t af[2][4], lf[2][4], bfp[2][4], cfp[2][4];
            LDSM4(af[0], ak);
            LDSM4(af[1], ak + 16 * SH * 2);
            LDSM4(lf[0], ak + TILEB);
            LDSM4(lf[1], ak + TILEB + 16 * SH * 2);
            LDSM4(bfp[0], bk);
            LDSM4(bfp[1], bk + 16 * SH * 2);
            LDSM4(cfp[0], bk + TILEB);
            LDSM4(cfp[1], bk + TILEB + 16 * SH * 2);

            #pragma unroll
            for (int mt = 0; mt < 2; ++mt)
                #pragma unroll
                for (int p = 0; p < 2; ++p) {
                    mma_f16(acc[mt][2 * p],      af[mt], &bfp[p][0]);
                    mma_f16(acc[mt][2 * p + 1],  af[mt], &bfp[p][2]);
                    mma_f16(corr[mt][2 * p],     lf[mt], &bfp[p][0]);
                    mma_f16(corr[mt][2 * p + 1], lf[mt], &bfp[p][2]);
                    mma_f16(corr[mt][2 * p],     af[mt], &cfp[p][0]);
                    mma_f16(corr[mt][2 * p + 1], af[mt], &cfp[p][2]);
                }
        }

        if (more) {
            char* st = dynsmem + (cur ^ 1) * STAGEB;
            uint4 h, l;
            cvt8(fa0, fa1, h, l);
            *reinterpret_cast<uint4*>(st + stOff)         = h;
            *reinterpret_cast<uint4*>(st + TILEB + stOff) = l;
            cvt8(fb0, fb1, h, l);
            *reinterpret_cast<uint4*>(st + 2 * TILEB + stOff) = h;
            *reinterpret_cast<uint4*>(st + 3 * TILEB + stOff) = l;
        }
        __syncthreads();
        cur ^= 1;
    }

    // -------- epilogue: combine, bias/beta/sigmoid -> g_p
    const int g = lane >> 2;
    const int t = lane & 3;
    const float INV2048 = 4.8828125e-4f;
    #pragma unroll
    for (int mt = 0; mt < 2; ++mt) {
        const int row = rowBase + wm * 32 + mt * 16 + g;
        #pragma unroll
        for (int nt = 0; nt < 4; ++nt) {
            const int cl  = wn * 32 + nt * 8 + 2 * t;        // block-local col
            const int col = colBase + cl;
            const float bb0 = bias_sh[cl],     bt0 = beta_sh[cl];
            const float bb1 = bias_sh[cl + 1], bt1 = beta_sh[cl + 1];
            float v0 = acc[mt][nt][0] + corr[mt][nt][0] * INV2048;
            float v1 = acc[mt][nt][1] + corr[mt][nt][1] * INV2048;
            float v2 = acc[mt][nt][2] + corr[mt][nt][2] * INV2048;
            float v3 = acc[mt][nt][3] + corr[mt][nt][3] * INV2048;
            float z0 = bt0 * (v0 + bb0);
            float z1 = bt1 * (v1 + bb1);
            float z2 = bt0 * (v2 + bb0);
            float z3 = bt1 * (v3 + bb1);
            float s0 = 1.f / (1.f + expf(-z0));
            float s1 = 1.f / (1.f + expf(-z1));
            float s2 = 1.f / (1.f + expf(-z2));
            float s3 = 1.f / (1.f + expf(-z3));
            if (col + 1 < NNODE) {
                *reinterpret_cast<float2*>(&g_p[(size_t)row * PSTR + col])       = make_float2(s0, s1);
                *reinterpret_cast<float2*>(&g_p[(size_t)(row + 8) * PSTR + col]) = make_float2(s2, s3);
            } else if (col < NNODE) {
                g_p[(size_t)row * PSTR + col]       = s0;
                g_p[(size_t)(row + 8) * PSTR + col] = s2;
            }
        }
    }
}

// ---------------- leaf softmax (Q and transposed logQ) -----------------------
__global__ void k_softmax(const float* __restrict__ lp)
{
    __shared__ float redm[4], reds[4];
    int leaf = blockIdx.x, c = threadIdx.x;    // 128 threads
    int lane = c & 31, w = c >> 5;
    float v = lp[leaf * NC + c];
    float m = v;
    #pragma unroll
    for (int off = 16; off; off >>= 1) m = fmaxf(m, __shfl_xor_sync(0xffffffffu, m, off));
    if (lane == 0) redm[w] = m;
    __syncthreads();
    m = fmaxf(fmaxf(redm[0], redm[1]), fmaxf(redm[2], redm[3]));
    float e = expf(v - m);
    float s = e;
    #pragma unroll
    for (int off = 16; off; off >>= 1) s += __shfl_xor_sync(0xffffffffu, s, off);
    if (lane == 0) reds[w] = s;
    __syncthreads();
    s = reds[0] + reds[1] + reds[2] + reds[3];
    g_Q[leaf * NC + c] = e / s;
    g_logQt[c * NLEAF + leaf] = v - m - logf(s);
}

// ======== path: 2 samples/warp register tree + fused finalize ================
// Lanes <-> 32 depth-5 nodes. Depths 0..4 propagate via shuffles; depths 5..7
// gates are direct per-lane loads. Two independent sample chains per warp
// interleave in the pipeline; penalty sums accumulate in registers across both
// samples, then one predicated smem-atomic pass, then one block->global pass.
// NOTE: output rows start at out+1 (4B-aligned only) -> scalar stores.
#define SPW 2    // samples per warp
__global__ __launch_bounds__(256)
void k_path(const int* __restrict__ target, float* __restrict__ out, int outOffset)
{
    __shared__ float s_num[128];
    __shared__ float s_den[128];
    __shared__ float s_loss;
    __shared__ unsigned s_rank;
    __shared__ float s_red[128];

    const int tid  = threadIdx.x;
    const int lane = tid & 31;
    const int wid  = tid >> 5;
    const unsigned FULL = 0xffffffffu;

    if (tid < 128) { s_num[tid] = 0.f; s_den[tid] = 0.f; }
    if (tid == 0)  s_loss = 0.f;
    __syncthreads();

    // register penalty accumulators (per-lane meaning):
    // aN[d], d<5 : node (2^d-1)+lane   (valid for lane < 2^d)
    // aN[5]      : node 31+lane
    // aN[6],aN[7]: nodes 63+2*lane, 64+2*lane
    float aN[8], aD[8];
    #pragma unroll
    for (int i = 0; i < 8; ++i) { aN[i] = 0.f; aD[i] = 0.f; }
    float lsumW = 0.f;

    #pragma unroll
    for (int it = 0; it < SPW; ++it) {
        const int s = blockIdx.x * (8 * SPW) + wid * SPW + it;
        const float* pr = g_p + (size_t)s * PSTR;
        float pS  = pr[lane];                 // nodes 0..30 (lane 31 unused)
        float p5  = pr[31 + lane];            // depth-5 gate
        float g60 = pr[63 + 2 * lane];        // depth-6 gates
        float g61 = pr[64 + 2 * lane];
        float g70 = pr[127 + 4 * lane];       // depth-7 gates
        float g71 = pr[128 + 4 * lane];
        float g72 = pr[129 + 4 * lane];
        float g73 = pr[130 + 4 * lane];

        // depths 0..4: lane j (< 2^d) holds path to node (2^d-1)+j
        float path = 1.f;
        #pragma unroll
        for (int d = 0; d < 5; ++d) {
            const int w = 1 << d;
            float pv = __shfl_sync(FULL, pS, ((w - 1) + lane) & 31);
            if (lane < w) { aN[d] += pv * path; aD[d] += path; }
            float pp = __shfl_sync(FULL, path, lane >> 1);
            float pg = __shfl_sync(FULL, pS, ((w - 1) + (lane >> 1)) & 31);
            float f  = (lane & 1) ? pg : (1.f - pg);
            float np = pp * f;
            if (lane < 2 * w) path = np;
        }
        // path = path to depth-5 node 31+lane (all 32 lanes valid)
        aN[5] += p5 * path; aD[5] += path;
        float c0 = path * (1.f - p5);
        float c1 = path * p5;
        aN[6] += g60 * c0; aD[6] += c0;
        aN[7] += g61 * c1; aD[7] += c1;
        float e0 = c0 * (1.f - g60), e1 = c0 * g60;
        float e2 = c1 * (1.f - g61), e3 = c1 * g61;
        float L[8];
        L[0] = e0 * (1.f - g70); L[1] = e0 * g70;
        L[2] = e1 * (1.f - g71); L[3] = e1 * g71;
        L[4] = e2 * (1.f - g72); L[5] = e2 * g72;
        L[6] = e3 * (1.f - g73); L[7] = e3 * g73;

        // loss + argmax
        const int t = target[s];
        const float* lq = g_logQt + (size_t)t * NLEAF + 8 * lane;
        float4 q0 = *reinterpret_cast<const float4*>(lq);
        float4 q1 = *reinterpret_cast<const float4*>(lq + 4);
        float lsum = L[0] * q0.x + L[1] * q0.y + L[2] * q0.z + L[3] * q0.w
                   + L[4] * q1.x + L[5] * q1.y + L[6] * q1.z + L[7] * q1.w;
        float bv = L[0]; int bi = 8 * lane;
        #pragma unroll
        for (int k = 1; k < 8; ++k)
            if (L[k] > bv) { bv = L[k]; bi = 8 * lane + k; }   // strict: first max
        #pragma unroll
        for (int off = 16; off; off >>= 1) {
            float ov = __shfl_down_sync(FULL, bv, off);
            int   oi = __shfl_down_sync(FULL, bi, off);
            float os = __shfl_down_sync(FULL, lsum, off);
            lsum += os;
            if (ov > bv || (ov == bv && oi < bi)) { bv = ov; bi = oi; }
        }
        bi = __shfl_sync(FULL, bi, 0);
        if (lane == 0) lsumW += lsum;

        // output row: out[s] = Q[leaf]  (dst 4B-aligned only -> scalar stores)
        {
            const float4* qrow = reinterpret_cast<const float4*>(g_Q + (size_t)bi * NC);
            float4 qv = qrow[lane];
            float* orow = out + outOffset + (size_t)s * NC + 4 * lane;
            orow[0] = qv.x;
            orow[1] = qv.y;
            orow[2] = qv.z;
            orow[3] = qv.w;
        }
    }

    // warp-level register sums -> block smem (one predicated pass)
    #pragma unroll
    for (int d = 0; d < 5; ++d) {
        const int w = 1 << d;
        if (lane < w) {
            atomicAdd(&s_num[(w - 1) + lane], aN[d]);
            atomicAdd(&s_den[(w - 1) + lane], aD[d]);
        }
    }
    atomicAdd(&s_num[31 + lane], aN[5]);
    atomicAdd(&s_den[31 + lane], aD[5]);
    atomicAdd(&s_num[63 + 2 * lane], aN[6]);
    atomicAdd(&s_den[63 + 2 * lane], aD[6]);
    atomicAdd(&s_num[64 + 2 * lane], aN[7]);
    atomicAdd(&s_den[64 + 2 * lane], aD[7]);
    if (lane == 0) atomicAdd(&s_loss, lsumW);

    __syncthreads();
    if (tid < 127) {
        atomicAdd(&g_pen_num[tid], s_num[tid]);
        atomicAdd(&g_pen_den[tid], s_den[tid]);
    }
    if (tid == 0) atomicAdd(&g_loss, s_loss);

    // -------- fused finalize: last block computes total -> out[0]
    __threadfence();
    if (tid == 0) s_rank = atomicAdd(&g_done, 1u);
    __syncthreads();
    if (s_rank == gridDim.x - 1) {
        float v = 0.f;
        if (tid < 127) {
            float num = *((volatile float*)&g_pen_num[tid]);
            float den = *((volatile float*)&g_pen_den[tid]);
            float pen = num / den;
            int dd = 31 - __clz(tid + 1);                 // depth of node tid
            float lam = 0.1f * exp2f(-(float)(dd + 1));
            v = -lam * 0.5f * (logf(pen) + logf(1.f - pen));
        }
        if (tid < 128) s_red[tid] = v;
        __syncthreads();
        if (tid == 0) {
            float Cpen = 0.f;
            for (int i = 0; i < 127; ++i) Cpen += s_red[i];
            float loss = (*((volatile float*)&g_loss)) / (float)BB;
            if (outOffset >= 1) out[0] = -loss + Cpen;
        }
    }
}

// ---------------- launch -----------------------------------------------------
extern "C" void kernel_launch(void* const* d_in, const int* in_sizes, int n_in,
                              void* d_out, int out_size)
{
    const float* x      = (const float*)d_in[0];
    const int*   target = (const int*)  d_in[1];
    const float* W      = (const float*)d_in[2];
    const float* bias   = (const float*)d_in[3];
    const float* beta   = (const float*)d_in[4];
    const float* leafp  = (const float*)d_in[5];
    float* out = (float*)d_out;

    int offset = out_size - BB * NC;
    if (offset < 0) offset = 0;

    cudaFuncSetAttribute(k_gemm, cudaFuncAttributeMaxDynamicSharedMemorySize, DYNSME);

    k_init<<<1, 128>>>();

    dim3 gg(2, BB / 128);   // (2 N-tiles, 64 M-tiles) = 128 CTAs
    k_gemm<<<gg, 512, DYNSME>>>(x, W, bias, beta);

    k_softmax<<<NLEAF, NC>>>(leafp);

    k_path<<<BB / (8 * SPW), 256>>>(target, out, offset);  // 512 blocks
}

// round 17
// speedup vs baseline: 2.8325x; 1.0188x over previous
#include <cuda_runtime.h>
#include <cuda_fp16.h>
#include <cstdint>

// Problem constants (fixed by setup_inputs)
#define BB    8192      // batch
#define DD    2048      // feature dim
#define NNODE 255      // inner nodes (2^8 - 1)
#define PSTR  256       // padded stride for p
#define NLEAF 256
#define NC    128       // classes

// ---------------- scratch (device globals; no dynamic allocation) ----------
__device__ float g_p[BB * PSTR];        // sigmoid gate per (sample, node)
__device__ float g_Q[NLEAF * NC];       // softmax(leaf_params)
__device__ float g_logQt[NC * NLEAF];   // transposed logQ: [class][leaf]
__device__ float g_pen_num[128];
__device__ float g_pen_den[128];
__device__ float g_loss;
__device__ unsigned g_rowdone[64];      // per-row-block ticket (2 CTAs each)
__device__ unsigned g_done;             // finisher ticket for finalize

// ---------------- init ------------------------------------------------------
__global__ void k_init() {
    int t = threadIdx.x;
    if (t < 128) { g_pen_num[t] = 0.f; g_pen_den[t] = 0.f; }
    if (t < 64)  g_rowdone[t] = 0u;
    if (t == 0)  { g_loss = 0.f; g_done = 0u; }
}

// ---------------- leaf softmax (Q and transposed logQ) -----------------------
// Launched BEFORE the gemm so the fused path can read g_Q / g_logQt.
__global__ void k_softmax(const float* __restrict__ lp)
{
    __shared__ float redm[4], reds[4];
    int leaf = blockIdx.x, c = threadIdx.x;    // 128 threads
    int lane = c & 31, w = c >> 5;
    float v = lp[leaf * NC + c];
    float m = v;
    #pragma unroll
    for (int off = 16; off; off >>= 1) m = fmaxf(m, __shfl_xor_sync(0xffffffffu, m, off));
    if (lane == 0) redm[w] = m;
    __syncthreads();
    m = fmaxf(fmaxf(redm[0], redm[1]), fmaxf(redm[2], redm[3]));
    float e = expf(v - m);
    float s = e;
    #pragma unroll
    for (int off = 16; off; off >>= 1) s += __shfl_xor_sync(0xffffffffu, s, off);
    if (lane == 0) reds[w] = s;
    __syncthreads();
    s = reds[0] + reds[1] + reds[2] + reds[3];
    g_Q[leaf * NC + c] = e / s;
    g_logQt[c * NLEAF + leaf] = v - m - logf(s);
}

// ================= fp16x3 tensor-core GEMM (mma.sync m16n8k16) ==============
// Split v = h + l (h = fp16 RN), store l' = l*2048 (always fp16-normal).
// acc  = Ah*Bh;  corr = Ah*Bl' + Al'*Bh;  final = acc + corr * 2^-11.
// CTA: 512 thr, 16 warps (4x4), block tile 128x128, warp tile 32x32, KC=32.
// FUSED TAIL: the second CTA of each row-block pair (ticket g_rowdone[by])
// runs the tree-path/loss/argmax/output for its 128 samples; last finisher
// (ticket g_done) computes the total into out[0].

#define KC     32
#define NCHK   (DD / KC)            // 64
#define SH     40                   // halves per smem row (80B; LDSM conflict-free)
#define TILEB  (128 * SH * 2)       // 10240 bytes per tile array
#define STAGEB (4 * TILEB)          // Ah, Al, Bh, Bl = 40960 bytes
#define DYNSME (2 * STAGEB)         // 81920 bytes

__device__ __forceinline__ uint32_t smem_u32(const void* p) {
    uint32_t a;
    asm("{ .reg .u64 t; cvta.to.shared.u64 t, %1; cvt.u32.u64 %0, t; }"
        : "=r"(a) : "l"(p));
    return a;
}

#define LDSM4(R, addr) \
    asm volatile("ldmatrix.sync.aligned.m8n8.x4.shared.b16 {%0,%1,%2,%3}, [%4];" \
        : "=r"((R)[0]), "=r"((R)[1]), "=r"((R)[2]), "=r"((R)[3]) : "r"(addr))

__device__ __forceinline__ void mma_f16(float* c, const uint32_t* a, const uint32_t* b) {
    asm volatile(
        "mma.sync.aligned.m16n8k16.row.col.f32.f16.f16.f32 "
        "{%0,%1,%2,%3}, {%4,%5,%6,%7}, {%8,%9}, {%0,%1,%2,%3};"
        : "+f"(c[0]), "+f"(c[1]), "+f"(c[2]), "+f"(c[3])
        : "r"(a[0]), "r"(a[1]), "r"(a[2]), "r"(a[3]), "r"(b[0]), "r"(b[1]));
}

// 8 floats -> uint4 of fp16-hi and uint4 of (lo*2048) fp16
__device__ __forceinline__ void cvt8(float4 f0, float4 f1, uint4& h, uint4& l) {
    __half2 h0 = __floats2half2_rn(f0.x, f0.y);
    __half2 h1 = __floats2half2_rn(f0.z, f0.w);
    __half2 h2 = __floats2half2_rn(f1.x, f1.y);
    __half2 h3 = __floats2half2_rn(f1.z, f1.w);
    float2 g0 = __half22float2(h0), g1 = __half22float2(h1);
    float2 g2 = __half22float2(h2), g3 = __half22float2(h3);
    __half2 l0 = __floats2half2_rn((f0.x - g0.x) * 2048.f, (f0.y - g0.y) * 2048.f);
    __half2 l1 = __floats2half2_rn((f0.z - g1.x) * 2048.f, (f0.w - g1.y) * 2048.f);
    __half2 l2 = __floats2half2_rn((f1.x - g2.x) * 2048.f, (f1.y - g2.y) * 2048.f);
    __half2 l3 = __floats2half2_rn((f1.z - g3.x) * 2048.f, (f1.w - g3.y) * 2048.f);
    h.x = *reinterpret_cast<uint32_t*>(&h0);
    h.y = *reinterpret_cast<uint32_t*>(&h1);
    h.z = *reinterpret_cast<uint32_t*>(&h2);
    h.w = *reinterpret_cast<uint32_t*>(&h3);
    l.x = *reinterpret_cast<uint32_t*>(&l0);
    l.y = *reinterpret_cast<uint32_t*>(&l1);
    l.z = *reinterpret_cast<uint32_t*>(&l2);
    l.w = *reinterpret_cast<uint32_t*>(&l3);
}

__global__ __launch_bounds__(512, 1)
void k_gemm(const float* __restrict__ x, const float* __restrict__ W,
            const float* __restrict__ bias, const float* __restrict__ beta,
            const int* __restrict__ target, float* __restrict__ out, int outOffset)
{
    extern __shared__ __align__(16) char dynsmem[];
    __shared__ float bias_sh[128], beta_sh[128];
    __shared__ float s_num[128], s_den[128];
    __shared__ float s_red[128];
    __shared__ float s_loss;
    __shared__ unsigned s_tick, s_rank;

    const int tid  = threadIdx.x;
    const int lane = tid & 31;
    const int wid  = tid >> 5;
    const int wm   = wid & 3;                   // warp M group (0..3)
    const int wn   = wid >> 2;                  // warp N group (0..3)
    const int rowBase = blockIdx.y * 128;
    const int colBase = blockIdx.x * 128;

    if (tid < 128) {
        int c = colBase + tid;
        bias_sh[tid] = (c < NNODE) ? bias[c] : 0.f;
        beta_sh[tid] = (c < NNODE) ? beta[c] : 0.f;
    }

    // -------- global load map: thread -> (row, 8 consecutive floats per chunk)
    const int ldRow = tid >> 2;                 // 0..127
    const int ldKf  = (tid & 3) * 8;            // float offset 0,8,16,24
    const float* pA = x + (size_t)(rowBase + ldRow) * DD + ldKf;
    int nrow = colBase + ldRow;
    if (nrow >= NNODE) nrow = 0;                // clamp; masked in epilogue
    const float* pB = W + (size_t)nrow * DD + ldKf;
    const uint32_t stOff = (uint32_t)(ldRow * SH + ldKf) * 2;  // byte off in tile

    const uint32_t smemBase = smem_u32(dynsmem);

    // -------- ldmatrix lane address bases (byte offsets within a tile array)
    const int q = lane >> 3, r = lane & 7;
    const uint32_t aOff = (uint32_t)(((wm * 32 + (q & 1) * 8 + r) * SH + (q >> 1) * 8) * 2);
    const uint32_t bOff = (uint32_t)(((wn * 32 + (q >> 1) * 8 + r) * SH + (q & 1) * 8) * 2);

    float acc[2][4][4], corr[2][4][4];
    #pragma unroll
    for (int mt = 0; mt < 2; ++mt)
        #pragma unroll
        for (int nt = 0; nt < 4; ++nt)
            #pragma unroll
            for (int qq = 0; qq < 4; ++qq) { acc[mt][nt][qq] = 0.f; corr[mt][nt][qq] = 0.f; }

    // -------- prologue: chunk 0 -> stage 0
    {
        float4 fa0 = *reinterpret_cast<const float4*>(pA);
        float4 fa1 = *reinterpret_cast<const float4*>(pA + 4);
        float4 fb0 = *reinterpret_cast<const float4*>(pB);
        float4 fb1 = *reinterpret_cast<const float4*>(pB + 4);
        uint4 h, l;
        char* st = dynsmem;
        cvt8(fa0, fa1, h, l);
        *reinterpret_cast<uint4*>(st + stOff)         = h;
        *reinterpret_cast<uint4*>(st + TILEB + stOff) = l;
        cvt8(fb0, fb1, h, l);
        *reinterpret_cast<uint4*>(st + 2 * TILEB + stOff) = h;
        *reinterpret_cast<uint4*>(st + 3 * TILEB + stOff) = l;
    }
    __syncthreads();

    int cur = 0;
    for (int kt = 0; kt < NCHK; ++kt) {
        const bool more = (kt + 1 < NCHK);
        float4 fa0, fa1, fb0, fb1;
        if (more) {
            fa0 = *reinterpret_cast<const float4*>(pA + (kt + 1) * KC);
            fa1 = *reinterpret_cast<const float4*>(pA + (kt + 1) * KC + 4);
            fb0 = *reinterpret_cast<const float4*>(pB + (kt + 1) * KC);
            fb1 = *reinterpret_cast<const float4*>(pB + (kt + 1) * KC + 4);
        }

        const uint32_t sb = smemBase + (uint32_t)cur * STAGEB;
        #pragma unroll
        for (int ksec = 0; ksec < 2; ++ksec) {
            const uint32_t ak = sb + aOff + ksec * 32;
            const uint32_t bk = sb + 2 * TILEB + bOff + ksec * 32;
            uint32_t af[2][4], lf[2][4], bfp[2][4], cfp[2][4];
            LDSM4(af[0], ak);
            LDSM4(af[1], ak + 16 * SH * 2);
            LDSM4(lf[0], ak + TILEB);
            LDSM4(lf[1], ak + TILEB + 16 * SH * 2);
            LDSM4(bfp[0], bk);
            LDSM4(bfp[1], bk + 16 * SH * 2);
            LDSM4(cfp[0], bk + TILEB);
            LDSM4(cfp[1], bk + TILEB + 16 * SH * 2);

            #pragma unroll
            for (int mt = 0; mt < 2; ++mt)
                #pragma unroll
                for (int p = 0; p < 2; ++p) {
                    mma_f16(acc[mt][2 * p],      af[mt], &bfp[p][0]);
                    mma_f16(acc[mt][2 * p + 1],  af[mt], &bfp[p][2]);
                    mma_f16(corr[mt][2 * p],     lf[mt], &bfp[p][0]);
                    mma_f16(corr[mt][2 * p + 1], lf[mt], &bfp[p][2]);
                    mma_f16(corr[mt][2 * p],     af[mt], &cfp[p][0]);
                    mma_f16(corr[mt][2 * p + 1], af[mt], &cfp[p][2]);
                }
        }

        if (more) {
            char* st = dynsmem + (cur ^ 1) * STAGEB;
            uint4 h, l;
            cvt8(fa0, fa1, h, l);
            *reinterpret_cast<uint4*>(st + stOff)         = h;
            *reinterpret_cast<uint4*>(st + TILEB + stOff) = l;
            cvt8(fb0, fb1, h, l);
            *reinterpret_cast<uint4*>(st + 2 * TILEB + stOff) = h;
            *reinterpret_cast<uint4*>(st + 3 * TILEB + stOff) = l;
        }
        __syncthreads();
        cur ^= 1;
    }

    // -------- epilogue: combine, bias/beta/sigmoid -> g_p
    {
        const int g = lane >> 2;
        const int t = lane & 3;
        const float INV2048 = 4.8828125e-4f;
        #pragma unroll
        for (int mt = 0; mt < 2; ++mt) {
            const int row = rowBase + wm * 32 + mt * 16 + g;
            #pragma unroll
            for (int nt = 0; nt < 4; ++nt) {
                const int cl  = wn * 32 + nt * 8 + 2 * t;        // block-local col
                const int col = colBase + cl;
                const float bb0 = bias_sh[cl],     bt0 = beta_sh[cl];
                const float bb1 = bias_sh[cl + 1], bt1 = beta_sh[cl + 1];
                float v0 = acc[mt][nt][0] + corr[mt][nt][0] * INV2048;
                float v1 = acc[mt][nt][1] + corr[mt][nt][1] * INV2048;
                float v2 = acc[mt][nt][2] + corr[mt][nt][2] * INV2048;
                float v3 = acc[mt][nt][3] + corr[mt][nt][3] * INV2048;
                float z0 = bt0 * (v0 + bb0);
                float z1 = bt1 * (v1 + bb1);
                float z2 = bt0 * (v2 + bb0);
                float z3 = bt1 * (v3 + bb1);
                float s0 = 1.f / (1.f + expf(-z0));
                float s1 = 1.f / (1.f + expf(-z1));
                float s2 = 1.f / (1.f + expf(-z2));
                float s3 = 1.f / (1.f + expf(-z3));
                if (col + 1 < NNODE) {
                    *reinterpret_cast<float2*>(&g_p[(size_t)row * PSTR + col])       = make_float2(s0, s1);
                    *reinterpret_cast<float2*>(&g_p[(size_t)(row + 8) * PSTR + col]) = make_float2(s2, s3);
                } else if (col < NNODE) {
                    g_p[(size_t)row * PSTR + col]       = s0;
                    g_p[(size_t)(row + 8) * PSTR + col] = s2;
                }
            }
        }
    }

    // ================= fused path tail ======================================
    // ticket: second CTA of this row-block pair runs the path for 128 samples
    __threadfence();
    __syncthreads();
    if (tid == 0) s_tick = atomicAdd(&g_rowdone[blockIdx.y], 1u);
    __syncthreads();
    if (s_tick != 1u) return;          // first finisher exits
    __threadfence();                   // see the other CTA's g_p stores

    const unsigned FULL = 0xffffffffu;
    if (tid < 128) { s_num[tid] = 0.f; s_den[tid] = 0.f; }
    if (tid == 0)  s_loss = 0.f;
    __syncthreads();

    // register penalty accumulators (per-lane meaning):
    // aN[d], d<5 : node (2^d-1)+lane (valid lane<2^d); aN[5]: 31+lane;
    // aN[6],aN[7]: 63+2*lane, 64+2*lane
    float aN[8], aD[8];
    #pragma unroll
    for (int i = 0; i < 8; ++i) { aN[i] = 0.f; aD[i] = 0.f; }
    float lsumW = 0.f;

    #pragma unroll
    for (int it = 0; it < 8; ++it) {               // 16 warps x 8 samples = 128
        const int s = rowBase + wid * 8 + it;
        const float* pr = g_p + (size_t)s * PSTR;
        float pS  = pr[lane];                 // nodes 0..30 (lane 31 unused)
        float p5  = pr[31 + lane];            // depth-5 gate
        float g60 = pr[63 + 2 * lane];        // depth-6 gates
        float g61 = pr[64 + 2 * lane];
        float g70 = pr[127 + 4 * lane];       // depth-7 gates
        float g71 = pr[128 + 4 * lane];
        float g72 = pr[129 + 4 * lane];
        float g73 = pr[130 + 4 * lane];

        float path = 1.f;
        #pragma unroll
        for (int d = 0; d < 5; ++d) {
            const int w = 1 << d;
            float pv = __shfl_sync(FULL, pS, ((w - 1) + lane) & 31);
            if (lane < w) { aN[d] += pv * path; aD[d] += path; }
            float pp = __shfl_sync(FULL, path, lane >> 1);
            float pg = __shfl_sync(FULL, pS, ((w - 1) + (lane >> 1)) & 31);
            float f  = (lane & 1) ? pg : (1.f - pg);
            float np = pp * f;
            if (lane < 2 * w) path = np;
        }
        aN[5] += p5 * path; aD[5] += path;
        float c0 = path * (1.f - p5);
        float c1 = path * p5;
        aN[6] += g60 * c0; aD[6] += c0;
        aN[7] += g61 * c1; aD[7] += c1;
        float e0 = c0 * (1.f - g60), e1 = c0 * g60;
        float e2 = c1 * (1.f - g61), e3 = c1 * g61;
        float L[8];
        L[0] = e0 * (1.f - g70); L[1] = e0 * g70;
        L[2] = e1 * (1.f - g71); L[3] = e1 * g71;
        L[4] = e2 * (1.f - g72); L[5] = e2 * g72;
        L[6] = e3 * (1.f - g73); L[7] = e3 * g73;

        // loss + argmax
        const int tg = target[s];
        const float* lq = g_logQt + (size_t)tg * NLEAF + 8 * lane;
        float4 q0 = *reinterpret_cast<const float4*>(lq);
        float4 q1 = *reinterpret_cast<const float4*>(lq + 4);
        float lsum = L[0] * q0.x + L[1] * q0.y + L[2] * q0.z + L[3] * q0.w
                   + L[4] * q1.x + L[5] * q1.y + L[6] * q1.z + L[7] * q1.w;
        float bv = L[0]; int bi = 8 * lane;
        #pragma unroll
        for (int k = 1; k < 8; ++k)
            if (L[k] > bv) { bv = L[k]; bi = 8 * lane + k; }   // strict: first max
        #pragma unroll
        for (int off = 16; off; off >>= 1) {
            float ov = __shfl_down_sync(FULL, bv, off);
            int   oi = __shfl_down_sync(FULL, bi, off);
            float os = __shfl_down_sync(FULL, lsum, off);
            lsum += os;
            if (ov > bv || (ov == bv && oi < bi)) { bv = ov; bi = oi; }
        }
        bi = __shfl_sync(FULL, bi, 0);
        if (lane == 0) lsumW += lsum;

        // output row (dst 4B-aligned only -> scalar stores)
        {
            const float4* qrow = reinterpret_cast<const float4*>(g_Q + (size_t)bi * NC);
            float4 qv = qrow[lane];
            float* orow = out + outOffset + (size_t)s * NC + 4 * lane;
            orow[0] = qv.x;
            orow[1] = qv.y;
            orow[2] = qv.z;
            orow[3] = qv.w;
        }
    }

    // warp-level register sums -> block smem (one predicated pass)
    #pragma unroll
    for (int d = 0; d < 5; ++d) {
        const int w = 1 << d;
        if (lane < w) {
            atomicAdd(&s_num[(w - 1) + lane], aN[d]);
            atomicAdd(&s_den[(w - 1) + lane], aD[d]);
        }
    }
    atomicAdd(&s_num[31 + lane], aN[5]);
    atomicAdd(&s_den[31 + lane], aD[5]);
    atomicAdd(&s_num[63 + 2 * lane], aN[6]);
    atomicAdd(&s_den[63 + 2 * lane], aD[6]);
    atomicAdd(&s_num[64 + 2 * lane], aN[7]);
    atomicAdd(&s_den[64 + 2 * lane], aD[7]);
    if (lane == 0) atomicAdd(&s_loss, lsumW);

    __syncthreads();
    if (tid < 127) {
        atomicAdd(&g_pen_num[tid], s_num[tid]);
        atomicAdd(&g_pen_den[tid], s_den[tid]);
    }
    if (tid == 0) atomicAdd(&g_loss, s_loss);

    // -------- fused finalize: last finisher computes total -> out[0]
    __threadfence();
    if (tid == 0) s_rank = atomicAdd(&g_done, 1u);
    __syncthreads();
    if (s_rank == gridDim.y - 1) {
        float v = 0.f;
        if (tid < 127) {
            float num = *((volatile float*)&g_pen_num[tid]);
            float den = *((volatile float*)&g_pen_den[tid]);
            float pen = num / den;
            int dd = 31 - __clz(tid + 1);                 // depth of node tid
            float lam = 0.1f * exp2f(-(float)(dd + 1));
            v = -lam * 0.5f * (logf(pen) + logf(1.f - pen));
        }
        if (tid < 128) s_red[tid] = v;
        __syncthreads();
        if (tid == 0) {
            float Cpen = 0.f;
            for (int i = 0; i < 127; ++i) Cpen += s_red[i];
            float loss = (*((volatile float*)&g_loss)) / (float)BB;
            if (outOffset >= 1) out[0] = -loss + Cpen;
        }
    }
}

// ---------------- launch -----------------------------------------------------
extern "C" void kernel_launch(void* const* d_in, const int* in_sizes, int n_in,
                              void* d_out, int out_size)
{
    const float* x      = (const float*)d_in[0];
    const int*   target = (const int*)  d_in[1];
    const float* W      = (const float*)d_in[2];
    const float* bias   = (const float*)d_in[3];
    const float* beta   = (const float*)d_in[4];
    const float* leafp  = (const float*)d_in[5];
    float* out = (float*)d_out;

    int offset = out_size - BB * NC;
    if (offset < 0) offset = 0;

    cudaFuncSetAttribute(k_gemm, cudaFuncAttributeMaxDynamicSharedMemorySize, DYNSME);

    k_init<<<1, 128>>>();

    k_softmax<<<NLEAF, NC>>>(leafp);            // before gemm: fused path reads Q/logQt

    dim3 gg(2, BB / 128);   // (2 N-tiles, 64 M-tiles) = 128 CTAs
    k_gemm<<<gg, 512, DYNSME>>>(x, W, bias, beta, target, out, offset);
}